// round 3
// baseline (speedup 1.0000x reference)
#include <cuda_runtime.h>
#include <cstdint>

// Problem constants: B=4, C=192, S=64, L=512
#define Bx 4
#define Cc 192
#define Ss 64
#define Ll 512
#define SL (Ss*Ll)            // 32768
#define CSL ((size_t)Cc*SL)   // 6291456

// Scratch (device globals: no allocation allowed)
__device__ float g_wvT[Cc*Cc];   // wvT[k*192+c] = wv[c][k]
__device__ float g_woT[Cc*Cc];   // woT[k*192+o] = wo[o][k]
__device__ float g_ctx[Bx*Ss*Cc]; // ctx[(b*64+s)*192 + c]

// ---------------- f32x2 helpers ----------------
__device__ __forceinline__ void fma2(unsigned long long& d, unsigned long long a, unsigned long long b){
    asm("fma.rn.f32x2 %0, %1, %2, %0;" : "+l"(d) : "l"(a), "l"(b));
}
__device__ __forceinline__ unsigned long long dupf(float v){
    unsigned long long r; asm("mov.b64 %0, {%1, %1};" : "=l"(r) : "f"(v)); return r;
}
__device__ __forceinline__ void unpack2(unsigned long long p, float& lo, float& hi){
    asm("mov.b64 {%0, %1}, %2;" : "=f"(lo), "=f"(hi) : "l"(p));
}

// ---------------- K0: weight transposes ----------------
__global__ void k_prep(const float* __restrict__ ipw, const float* __restrict__ opw){
    int i = blockIdx.x*256 + threadIdx.x;
    if (i < Cc*Cc){
        int k = i / Cc, c = i % Cc;
        // ipw rows: 0 = wq, 1..192 = wk, 193..384 = wv
        g_wvT[k*Cc + c] = ipw[(size_t)(1+Cc+c)*Cc + k];
        g_woT[k*Cc + c] = opw[(size_t)c*Cc + k];
    }
}

// ---------------- K1: q-dot + softmax + weighted key-sum + context ----------------
// One block per (b,s). 256 threads.
__global__ void __launch_bounds__(256) k_stage1(
    const float* __restrict__ query, const float* __restrict__ key,
    const float* __restrict__ ipw,   const float* __restrict__ ipb)
{
    __shared__ float wq_s[Cc];
    __shared__ float sc[Ll];
    __shared__ float kb_s[Cc];
    __shared__ float red[8];
    __shared__ float bcast;

    int tid = threadIdx.x;
    int bs  = blockIdx.x;
    int b = bs >> 6, s = bs & 63;
    int warp = tid >> 5, lane = tid & 31;

    if (tid < Cc) wq_s[tid] = ipw[tid];           // wq = row 0
    __syncthreads();

    // ---- q[l] = wq . query[b,:,s,l] + bq ----
    const float* qb = query + (size_t)b*CSL + (size_t)s*Ll;
    float q0 = ipb[0], q1 = ipb[0];
    #pragma unroll 4
    for (int c = 0; c < Cc; c++){
        float w = wq_s[c];
        q0 = fmaf(w, qb[(size_t)c*SL + tid      ], q0);
        q1 = fmaf(w, qb[(size_t)c*SL + tid + 256], q1);
    }

    // ---- softmax over L=512 ----
    float m = fmaxf(q0, q1);
    #pragma unroll
    for (int o = 16; o; o >>= 1) m = fmaxf(m, __shfl_xor_sync(0xffffffffu, m, o));
    if (!lane) red[warp] = m;
    __syncthreads();
    if (tid == 0){ float mm = red[0]; for (int i = 1; i < 8; i++) mm = fmaxf(mm, red[i]); bcast = mm; }
    __syncthreads();
    float M = bcast;
    float e0 = expf(q0 - M), e1 = expf(q1 - M);
    float sum = e0 + e1;
    #pragma unroll
    for (int o = 16; o; o >>= 1) sum += __shfl_xor_sync(0xffffffffu, sum, o);
    __syncthreads();  // everyone has read bcast(M); safe to reuse
    if (!lane) red[warp] = sum;
    __syncthreads();
    if (tid == 0){ float ss = 0.f; for (int i = 0; i < 8; i++) ss += red[i]; bcast = 1.f/ss; }
    __syncthreads();
    float inv = bcast;
    sc[tid]       = e0 * inv;
    sc[tid + 256] = e1 * inv;
    __syncthreads();

    // ---- kbar[c] = sum_l key[b,c,s,l] * sc[l] ----
    const float* kbase = key + (size_t)b*CSL + (size_t)s*Ll;
    for (int c = warp; c < Cc; c += 8){
        const float* row = kbase + (size_t)c*SL;
        float a = 0.f;
        #pragma unroll 4
        for (int j = lane; j < Ll; j += 32) a = fmaf(row[j], sc[j], a);
        #pragma unroll
        for (int o = 16; o; o >>= 1) a += __shfl_xor_sync(0xffffffffu, a, o);
        if (!lane) kb_s[c] = a;
    }
    __syncthreads();

    // ---- ctx[c] = wk[c,:] . kbar + bk[c]   (softmax sums to 1, so bias passes through) ----
    if (tid < Cc){
        const float* wkr = ipw + (size_t)(1 + tid)*Cc;
        float a = ipb[1 + tid];
        #pragma unroll 4
        for (int j = 0; j < Cc; j++) a = fmaf(wkr[j], kb_s[j], a);
        g_ctx[(size_t)bs*Cc + tid] = a;
    }
}

// ---------------- K2: fused v-proj -> relu*ctx -> out-proj ----------------
// One block per (b, s, l-tile of 128). 512 threads, f32x2 FMA.
#define TL 128
#define WCH 32
#define SM_VAL   0                 // 192*128 floats
#define SM_WBUF  (Cc*TL)           // 32*192 floats
#define SM_CTX   (SM_WBUF + WCH*Cc)
#define SM_BV    (SM_CTX + Cc)
#define SM_BO    (SM_BV + Cc)
#define SM_FLOATS (SM_BO + Cc)

__device__ __forceinline__ void gemm_192(
    const float* __restrict__ Wg,  // transposed weights [k][c], 192x192
    float* valbuf, float* wbuf,
    int tx, int ty, int tid,
    unsigned long long acc[6][4])
{
    for (int kc = 0; kc < 6; kc++){
        // stage 32 weight rows (k-chunk) into smem
        #pragma unroll
        for (int j = 0; j < 3; j++){
            int f = tid + 512*j;  // 1536 float4s = 6144 floats
            ((float4*)wbuf)[f] = ((const float4*)(Wg + (size_t)kc*WCH*Cc))[f];
        }
        __syncthreads();
        #pragma unroll 8
        for (int k = 0; k < WCH; k++){
            int kk = kc*WCH + k;
            float4 va = *(const float4*)(valbuf + (size_t)kk*TL + (tx << 2));
            unsigned long long v0 = dupf(va.x), v1 = dupf(va.y), v2 = dupf(va.z), v3 = dupf(va.w);
            const ulonglong2* wp = (const ulonglong2*)(wbuf + k*Cc + ty*12);
            ulonglong2 wA = wp[0], wB = wp[1], wC = wp[2];
            unsigned long long w2[6] = {wA.x, wA.y, wB.x, wB.y, wC.x, wC.y};
            #pragma unroll
            for (int j = 0; j < 6; j++){
                fma2(acc[j][0], w2[j], v0);
                fma2(acc[j][1], w2[j], v1);
                fma2(acc[j][2], w2[j], v2);
                fma2(acc[j][3], w2[j], v3);
            }
        }
        __syncthreads();
    }
}

__global__ void __launch_bounds__(512, 1) k_main(
    const float* __restrict__ value,
    const float* __restrict__ ipb, const float* __restrict__ opb,
    float* __restrict__ out)
{
    extern __shared__ float sm[];
    float* val   = sm + SM_VAL;
    float* wbuf  = sm + SM_WBUF;
    float* ctx_s = sm + SM_CTX;
    float* bv_s  = sm + SM_BV;
    float* bo_s  = sm + SM_BO;

    int blk = blockIdx.x;
    int lt = blk & 3;            // l-tile
    int bs = blk >> 2;
    int b = bs >> 6, s = bs & 63;
    int l0 = lt * TL;
    int tid = threadIdx.x;
    int tx = tid & 31;           // l-quad: l = 4*tx .. 4*tx+3
    int ty = tid >> 5;           // 16 groups, 12 c-rows each
    int cbase = ty * 12;

    if (tid < Cc){
        ctx_s[tid] = g_ctx[(size_t)bs*Cc + tid];
        bv_s[tid]  = ipb[1 + Cc + tid];
        bo_s[tid]  = opb[tid];
    }

    // load value tile [192][128] (l contiguous)
    const float* vb = value + (size_t)b*CSL + (size_t)s*Ll + l0;
    #pragma unroll
    for (int j = 0; j < 12; j++){
        int f = tid + 512*j;                 // 0..6143 float4s
        int row = f >> 5, col = f & 31;
        ((float4*)val)[f] = *(const float4*)(vb + (size_t)row*SL + (col << 2));
    }
    __syncthreads();

    unsigned long long acc[6][4];
    #pragma unroll
    for (int j = 0; j < 6; j++)
        #pragma unroll
        for (int i = 0; i < 4; i++) acc[j][i] = 0ull;

    // GEMM1: v = wv @ val
    gemm_192(g_wvT, val, wbuf, tx, ty, tid, acc);

    // epilogue1: t = relu(v + bv) * ctx, written back into val buffer
    #pragma unroll
    for (int j = 0; j < 6; j++){
        int c = cbase + 2*j;
        float bl = bv_s[c], bh = bv_s[c+1];
        float gl = ctx_s[c], gh = ctx_s[c+1];
        float4 rl, rh; float lo, hi;
        unpack2(acc[j][0], lo, hi); rl.x = fmaxf(lo+bl, 0.f)*gl; rh.x = fmaxf(hi+bh, 0.f)*gh;
        unpack2(acc[j][1], lo, hi); rl.y = fmaxf(lo+bl, 0.f)*gl; rh.y = fmaxf(hi+bh, 0.f)*gh;
        unpack2(acc[j][2], lo, hi); rl.z = fmaxf(lo+bl, 0.f)*gl; rh.z = fmaxf(hi+bh, 0.f)*gh;
        unpack2(acc[j][3], lo, hi); rl.w = fmaxf(lo+bl, 0.f)*gl; rh.w = fmaxf(hi+bh, 0.f)*gh;
        *(float4*)(val + (size_t)c    *TL + (tx << 2)) = rl;
        *(float4*)(val + (size_t)(c+1)*TL + (tx << 2)) = rh;
    }

    #pragma unroll
    for (int j = 0; j < 6; j++)
        #pragma unroll
        for (int i = 0; i < 4; i++) acc[j][i] = 0ull;

    // GEMM2: out = wo @ t  (sync inside gemm_192 orders t-writes before t-reads)
    gemm_192(g_woT, val, wbuf, tx, ty, tid, acc);

    // epilogue2: + bo, store
    float* ob = out + (size_t)b*CSL + (size_t)s*Ll + l0;
    #pragma unroll
    for (int j = 0; j < 6; j++){
        int o = cbase + 2*j;
        float bl = bo_s[o], bh = bo_s[o+1];
        float4 rl, rh; float lo, hi;
        unpack2(acc[j][0], lo, hi); rl.x = lo + bl; rh.x = hi + bh;
        unpack2(acc[j][1], lo, hi); rl.y = lo + bl; rh.y = hi + bh;
        unpack2(acc[j][2], lo, hi); rl.z = lo + bl; rh.z = hi + bh;
        unpack2(acc[j][3], lo, hi); rl.w = lo + bl; rh.w = hi + bh;
        *(float4*)(ob + (size_t)o    *SL + (tx << 2)) = rl;
        *(float4*)(ob + (size_t)(o+1)*SL + (tx << 2)) = rh;
    }
}

extern "C" void kernel_launch(void* const* d_in, const int* in_sizes, int n_in,
                              void* d_out, int out_size)
{
    const float* query = (const float*)d_in[0];
    const float* key   = (const float*)d_in[1];
    const float* value = (const float*)d_in[2];
    const float* ipw   = (const float*)d_in[3];
    const float* ipb   = (const float*)d_in[4];
    const float* opw   = (const float*)d_in[5];
    const float* opb   = (const float*)d_in[6];
    float* out = (float*)d_out;

    const int SMEM_BYTES = SM_FLOATS * 4;  // 125,568 B
    cudaFuncSetAttribute(k_main, cudaFuncAttributeMaxDynamicSharedMemorySize, SMEM_BYTES);

    k_prep<<<(Cc*Cc + 255)/256, 256>>>(ipw, opw);
    k_stage1<<<Bx*Ss, 256>>>(query, key, ipw, ipb);
    k_main<<<Bx*Ss*(Ll/TL), 512, SMEM_BYTES>>>(value, ipb, opb, out);
}

// round 7
// speedup vs baseline: 1.5776x; 1.5776x over previous
#include <cuda_runtime.h>
#include <cuda_bf16.h>
#include <cstdint>

// Problem constants: B=4, C=192, S=64, L=512
#define Bx 4
#define Cc 192
#define Ss 64
#define Ll 512
#define SL (Ss*Ll)            // 32768
#define CSL ((size_t)Cc*SL)   // 6291456

#define TL 128                // l-tile per block

// W packing: per 64-k chunk, [hi image][lo image]; each image 192 rows x 72 halves (64 data + 8 pad)
#define WPITCH 72
#define HIMG_E (Cc*WPITCH)        // 13824 elems
#define CHUNK_E (2*HIMG_E)        // 27648 elems
#define CHUNK_B (CHUNK_E*2)       // 55296 bytes
#define HIMG_B (HIMG_E*2)         // 27648 bytes

__device__ __align__(16) __nv_bfloat16 g_wvpack[3*CHUNK_E];
__device__ __align__(16) __nv_bfloat16 g_wopack[3*CHUNK_E];
__device__ float g_ctx[Bx*Ss*Cc];

// X smem: [k=192 rows][l], pitch 136 halves (128 data + 8 pad)
#define XPITCH 136

// dynamic smem layout (bytes)
#define SM_W0   0
#define SM_W1   CHUNK_B
#define SM_XH   (2*CHUNK_B)                 // 110592
#define SM_XL   (SM_XH + Cc*XPITCH*2)       // +52224
#define SM_CTX  (SM_XL + Cc*XPITCH*2)       // 215040
#define SM_BV   (SM_CTX + Cc*4)
#define SM_BO   (SM_BV + Cc*4)
#define DSMEM_BYTES (SM_BO + Cc*4)          // 217344

// ---------------- PTX helpers (base sm_103 target only) ----------------
__device__ __forceinline__ uint32_t smem_u32(const void* p){
    return (uint32_t)__cvta_generic_to_shared(p);
}
#define MBAR_INIT(a, n)  asm volatile("mbarrier.init.shared.b64 [%0], %1;" :: "r"(a), "r"(n) : "memory")
#define MBAR_EXPECT(a, n) asm volatile("mbarrier.arrive.expect_tx.shared.b64 _, [%0], %1;" :: "r"(a), "r"(n) : "memory")
// Bounded wait: protocol bug => wrong answer, never a hang.
#define MBAR_WAIT(a, ph) do { \
    uint32_t _m = (a); uint32_t _p = (ph); uint32_t _done = 0; \
    for (int _i = 0; _i < 2000000 && !_done; _i++){ \
        asm volatile("{\n\t.reg .pred p;\n\t" \
            "mbarrier.try_wait.parity.shared.b64 p, [%1], %2;\n\t" \
            "selp.b32 %0, 1, 0, p;\n\t}" : "=r"(_done) : "r"(_m), "r"(_p) : "memory"); \
    } } while(0)
#define BULK_CP(dst, src, bytes, mbar) \
    asm volatile("cp.async.bulk.shared::cta.global.mbarrier::complete_tx::bytes [%0], [%1], %2, [%3];" \
        :: "r"(dst), "l"(src), "r"(bytes), "r"(mbar) : "memory")
#define FENCE_ASYNC() asm volatile("fence.proxy.async.shared::cta;" ::: "memory")

__device__ __forceinline__ void ldsm4(uint32_t r[4], uint32_t a){
    asm volatile("ldmatrix.sync.aligned.m8n8.x4.shared.b16 {%0,%1,%2,%3}, [%4];"
        : "=r"(r[0]), "=r"(r[1]), "=r"(r[2]), "=r"(r[3]) : "r"(a));
}
__device__ __forceinline__ void ldsm4t(uint32_t r[4], uint32_t a){
    asm volatile("ldmatrix.sync.aligned.m8n8.x4.trans.shared.b16 {%0,%1,%2,%3}, [%4];"
        : "=r"(r[0]), "=r"(r[1]), "=r"(r[2]), "=r"(r[3]) : "r"(a));
}
__device__ __forceinline__ void mma16816(float d[4], const uint32_t a[4], uint32_t b0, uint32_t b1){
    asm volatile("mma.sync.aligned.m16n8k16.row.col.f32.bf16.bf16.f32 "
        "{%0,%1,%2,%3}, {%4,%5,%6,%7}, {%8,%9}, {%0,%1,%2,%3};"
        : "+f"(d[0]), "+f"(d[1]), "+f"(d[2]), "+f"(d[3])
        : "r"(a[0]), "r"(a[1]), "r"(a[2]), "r"(a[3]), "r"(b0), "r"(b1));
}
__device__ __forceinline__ uint32_t pack_bf2(float x, float y){
    __nv_bfloat16 a = __float2bfloat16(x), b = __float2bfloat16(y);
    return ((uint32_t)__bfloat16_as_ushort(b) << 16) | (uint32_t)__bfloat16_as_ushort(a);
}

// ---------------- K0: pack weights bf16 hi/lo, chunked [n][k] pitch-72 ----------------
__global__ void k_prep(const float* __restrict__ ipw, const float* __restrict__ opw){
    int i = blockIdx.x*256 + threadIdx.x;
    if (i >= Cc*Cc) return;
    int n = i / Cc, k = i % Cc;
    int kc = k >> 6, kk = k & 63;
    int off = kc*CHUNK_E + n*WPITCH + kk;
    {
        float w = ipw[(size_t)(1 + Cc + n)*Cc + k];          // wv[n][k]
        __nv_bfloat16 hi = __float2bfloat16(w);
        __nv_bfloat16 lo = __float2bfloat16(w - __bfloat162float(hi));
        g_wvpack[off]          = hi;
        g_wvpack[off + HIMG_E] = lo;
    }
    {
        float w = opw[(size_t)n*Cc + k];                      // wo[n][k]
        __nv_bfloat16 hi = __float2bfloat16(w);
        __nv_bfloat16 lo = __float2bfloat16(w - __bfloat162float(hi));
        g_wopack[off]          = hi;
        g_wopack[off + HIMG_E] = lo;
    }
}

// ---------------- K1: q-dot + softmax + weighted key-sum + context (proven) ----------------
__global__ void __launch_bounds__(256) k_stage1(
    const float* __restrict__ query, const float* __restrict__ key,
    const float* __restrict__ ipw,   const float* __restrict__ ipb)
{
    __shared__ float wq_s[Cc];
    __shared__ float sc[Ll];
    __shared__ float kb_s[Cc];
    __shared__ float red[8];
    __shared__ float bcast;

    int tid = threadIdx.x;
    int bs  = blockIdx.x;
    int b = bs >> 6, s = bs & 63;
    int warp = tid >> 5, lane = tid & 31;

    if (tid < Cc) wq_s[tid] = ipw[tid];
    __syncthreads();

    const float* qb = query + (size_t)b*CSL + (size_t)s*Ll;
    float q0 = ipb[0], q1 = ipb[0];
    #pragma unroll 4
    for (int c = 0; c < Cc; c++){
        float w = wq_s[c];
        q0 = fmaf(w, qb[(size_t)c*SL + tid      ], q0);
        q1 = fmaf(w, qb[(size_t)c*SL + tid + 256], q1);
    }

    float m = fmaxf(q0, q1);
    #pragma unroll
    for (int o = 16; o; o >>= 1) m = fmaxf(m, __shfl_xor_sync(0xffffffffu, m, o));
    if (!lane) red[warp] = m;
    __syncthreads();
    if (tid == 0){ float mm = red[0]; for (int i = 1; i < 8; i++) mm = fmaxf(mm, red[i]); bcast = mm; }
    __syncthreads();
    float M = bcast;
    float e0 = expf(q0 - M), e1 = expf(q1 - M);
    float sum = e0 + e1;
    #pragma unroll
    for (int o = 16; o; o >>= 1) sum += __shfl_xor_sync(0xffffffffu, sum, o);
    __syncthreads();
    if (!lane) red[warp] = sum;
    __syncthreads();
    if (tid == 0){ float ss = 0.f; for (int i = 0; i < 8; i++) ss += red[i]; bcast = 1.f/ss; }
    __syncthreads();
    float inv = bcast;
    sc[tid]       = e0 * inv;
    sc[tid + 256] = e1 * inv;
    __syncthreads();

    const float* kbase = key + (size_t)b*CSL + (size_t)s*Ll;
    for (int c = warp; c < Cc; c += 8){
        const float* row = kbase + (size_t)c*SL;
        float a = 0.f;
        #pragma unroll 4
        for (int j = lane; j < Ll; j += 32) a = fmaf(row[j], sc[j], a);
        #pragma unroll
        for (int o = 16; o; o >>= 1) a += __shfl_xor_sync(0xffffffffu, a, o);
        if (!lane) kb_s[c] = a;
    }
    __syncthreads();

    if (tid < Cc){
        const float* wkr = ipw + (size_t)(1 + tid)*Cc;
        float a = ipb[1 + tid];
        #pragma unroll 4
        for (int j = 0; j < Cc; j++) a = fmaf(wkr[j], kb_s[j], a);
        g_ctx[(size_t)bs*Cc + tid] = a;
    }
}

// ---------------- K2: mma.sync bf16 split fused v-proj -> relu*ctx -> out-proj ----------------
// 256 threads, 8 warps: warp (wid&3) -> n rows [48*(wid&3), +48) as 3 m16 tiles,
// (wid>>2) -> l cols [64*(wid>>2), +64) as 8 n8 tiles. D[n][l], A=W (ldsm), B=X (ldsm.trans).
__global__ void __launch_bounds__(256, 1) k_main(
    const float* __restrict__ value,
    const float* __restrict__ ipb, const float* __restrict__ opb,
    float* __restrict__ out)
{
    extern __shared__ char dsm[];
    __shared__ __align__(8) unsigned long long s_mb[2];

    float* ctx_s = (float*)(dsm + SM_CTX);
    float* bv_s  = (float*)(dsm + SM_BV);
    float* bo_s  = (float*)(dsm + SM_BO);

    const uint32_t base = smem_u32(dsm);
    const uint32_t mb0 = smem_u32(&s_mb[0]);
    const uint32_t mb1 = smem_u32(&s_mb[1]);

    int tid = threadIdx.x;
    int lane = tid & 31, wid = tid >> 5;
    int blk = blockIdx.x;
    int lt = blk & 3;
    int bs = blk >> 2;
    int b = bs >> 6, s = bs & 63;
    int l0t = lt * TL;

    // kick off W chunk 0 and 1 (GEMM1 = wv)
    if (tid == 0){
        MBAR_INIT(mb0, 1); MBAR_INIT(mb1, 1);
        FENCE_ASYNC();
        MBAR_EXPECT(mb0, CHUNK_B);
        BULK_CP(base + SM_W0, (const char*)g_wvpack, CHUNK_B, mb0);
        MBAR_EXPECT(mb1, CHUNK_B);
        BULK_CP(base + SM_W1, (const char*)g_wvpack + CHUNK_B, CHUNK_B, mb1);
    }

    for (int i = tid; i < Cc; i += 256){
        ctx_s[i] = g_ctx[(size_t)bs*Cc + i];
        bv_s[i]  = ipb[1 + Cc + i];
        bo_s[i]  = opb[i];
    }

    // ---- load value tile [192 c][128 l] fp32, split -> Xhi/Xlo bf16 [k][l] pitch 136 ----
    {
        const float* vb = value + (size_t)b*CSL + (size_t)s*Ll + l0t;
        char* xh = dsm + SM_XH;
        char* xl = dsm + SM_XL;
        #pragma unroll
        for (int it = 0; it < 24; it++){
            int f = tid + 256*it;            // 6144 float4 total
            int row = f >> 5, col = f & 31;  // col in float4 units
            float4 v = *(const float4*)(vb + (size_t)row*SL + (col << 2));
            __nv_bfloat16 hx = __float2bfloat16(v.x), hy = __float2bfloat16(v.y);
            __nv_bfloat16 hz = __float2bfloat16(v.z), hw = __float2bfloat16(v.w);
            uint2 hp, lp;
            hp.x = ((uint32_t)__bfloat16_as_ushort(hy) << 16) | (uint32_t)__bfloat16_as_ushort(hx);
            hp.y = ((uint32_t)__bfloat16_as_ushort(hw) << 16) | (uint32_t)__bfloat16_as_ushort(hz);
            lp.x = pack_bf2(v.x - __bfloat162float(hx), v.y - __bfloat162float(hy));
            lp.y = pack_bf2(v.z - __bfloat162float(hz), v.w - __bfloat162float(hw));
            int off = row*(XPITCH*2) + (col << 3);
            *(uint2*)(xh + off) = hp;
            *(uint2*)(xl + off) = lp;
        }
    }
    __syncthreads();

    // warp tiling
    int m0  = (wid & 3) * 48;
    int lw0 = (wid >> 2) * 64;
    int g = lane >> 2, t = lane & 3;
    int lmr = (lane & 7) | (((lane >> 3) & 1) << 3);  // ldmatrix row within 16
    int lmc = (lane >> 4) << 3;                        // 0 or 8

    float d[3][8][4];
    #pragma unroll
    for (int a = 0; a < 3; a++)
        #pragma unroll
        for (int nt = 0; nt < 8; nt++)
            #pragma unroll
            for (int q = 0; q < 4; q++) d[a][nt][q] = 0.f;

    const uint32_t xh_b = base + SM_XH;
    const uint32_t xl_b = base + SM_XL;

    for (int ci = 0; ci < 6; ci++){
        if (ci == 3){
            // ---- epilogue 1: t = relu(v+bv)*ctx -> bf16 split back into X smem ----
            // (all warps passed the post-chunk-2 __syncthreads => GEMM1 reads done)
            #pragma unroll
            for (int mt = 0; mt < 3; mt++){
                #pragma unroll
                for (int nt = 0; nt < 8; nt++){
                    int o0 = m0 + mt*16 + g;
                    int l  = lw0 + nt*8 + t*2;
                    #pragma unroll
                    for (int h = 0; h < 2; h++){
                        int o = o0 + h*8;
                        float v0 = fmaxf(d[mt][nt][2*h]     + bv_s[o], 0.f) * ctx_s[o];
                        float v1 = fmaxf(d[mt][nt][2*h + 1] + bv_s[o], 0.f) * ctx_s[o];
                        __nv_bfloat16 h0 = __float2bfloat16(v0), h1 = __float2bfloat16(v1);
                        uint32_t hp = ((uint32_t)__bfloat16_as_ushort(h1) << 16) | (uint32_t)__bfloat16_as_ushort(h0);
                        uint32_t lp = pack_bf2(v0 - __bfloat162float(h0), v1 - __bfloat162float(h1));
                        int off = o*(XPITCH*2) + l*2;
                        *(uint32_t*)(dsm + SM_XH + off) = hp;
                        *(uint32_t*)(dsm + SM_XL + off) = lp;
                    }
                }
            }
            #pragma unroll
            for (int a = 0; a < 3; a++)
                #pragma unroll
                for (int nt = 0; nt < 8; nt++)
                    #pragma unroll
                    for (int q = 0; q < 4; q++) d[a][nt][q] = 0.f;
            __syncthreads();
        }

        int buf = ci & 1;
        MBAR_WAIT(buf ? mb1 : mb0, (ci >> 1) & 1);

        uint32_t wb = base + (buf ? SM_W1 : SM_W0);
        int kc64 = (ci < 3 ? ci : ci - 3) * 64;

        #pragma unroll
        for (int ks = 0; ks < 4; ks++){
            // A fragments (weights), hi and lo
            uint32_t Ah[3][4], Al[3][4];
            #pragma unroll
            for (int mt = 0; mt < 3; mt++){
                uint32_t arow = (uint32_t)((m0 + mt*16 + lmr)*WPITCH + ks*16 + lmc) * 2u;
                ldsm4(Ah[mt], wb + arow);
                ldsm4(Al[mt], wb + HIMG_B + arow);
            }
            int kg = kc64 + ks*16;
            #pragma unroll
            for (int ntp = 0; ntp < 4; ntp++){
                uint32_t boff = (uint32_t)((kg + lmr)*XPITCH + lw0 + ntp*16 + lmc) * 2u;
                uint32_t Bh[4], Bl[4];
                ldsm4t(Bh, xh_b + boff);
                ldsm4t(Bl, xl_b + boff);
                #pragma unroll
                for (int mt = 0; mt < 3; mt++){
                    mma16816(d[mt][ntp*2],     Ah[mt], Bh[0], Bh[1]);
                    mma16816(d[mt][ntp*2],     Ah[mt], Bl[0], Bl[1]);
                    mma16816(d[mt][ntp*2],     Al[mt], Bh[0], Bh[1]);
                    mma16816(d[mt][ntp*2 + 1], Ah[mt], Bh[2], Bh[3]);
                    mma16816(d[mt][ntp*2 + 1], Ah[mt], Bl[2], Bl[3]);
                    mma16816(d[mt][ntp*2 + 1], Al[mt], Bh[2], Bh[3]);
                }
            }
        }
        __syncthreads();   // all warps done with this W buffer

        if (tid == 0 && ci < 4){
            int nc = ci + 2;   // next chunk into the just-freed buffer
            const char* src = (nc < 3) ? ((const char*)g_wvpack + nc*CHUNK_B)
                                       : ((const char*)g_wopack + (nc - 3)*CHUNK_B);
            uint32_t mb = (nc & 1) ? mb1 : mb0;
            MBAR_EXPECT(mb, CHUNK_B);
            BULK_CP(base + (nc & 1 ? SM_W1 : SM_W0), src, CHUNK_B, mb);
        }
    }

    // ---- epilogue 2: + bo, store to out [o][l] ----
    float* ob = out + (size_t)b*CSL + (size_t)s*Ll + l0t;
    #pragma unroll
    for (int mt = 0; mt < 3; mt++){
        #pragma unroll
        for (int nt = 0; nt < 8; nt++){
            int o0 = m0 + mt*16 + g;
            int l  = lw0 + nt*8 + t*2;
            #pragma unroll
            for (int h = 0; h < 2; h++){
                int o = o0 + h*8;
                float2 r;
                r.x = d[mt][nt][2*h]     + bo_s[o];
                r.y = d[mt][nt][2*h + 1] + bo_s[o];
                *(float2*)(ob + (size_t)o*SL + l) = r;
            }
        }
    }
}

extern "C" void kernel_launch(void* const* d_in, const int* in_sizes, int n_in,
                              void* d_out, int out_size)
{
    const float* query = (const float*)d_in[0];
    const float* key   = (const float*)d_in[1];
    const float* value = (const float*)d_in[2];
    const float* ipw   = (const float*)d_in[3];
    const float* ipb   = (const float*)d_in[4];
    const float* opw   = (const float*)d_in[5];
    const float* opb   = (const float*)d_in[6];
    float* out = (float*)d_out;

    cudaFuncSetAttribute(k_main, cudaFuncAttributeMaxDynamicSharedMemorySize, DSMEM_BYTES);

    k_prep<<<(Cc*Cc + 255)/256, 256>>>(ipw, opw);
    k_stage1<<<Bx*Ss, 256>>>(query, key, ipw, ipb);
    k_main<<<Bx*Ss*(Ll/TL), 256, DSMEM_BYTES>>>(value, ipb, opb, out);
}

// round 8
// speedup vs baseline: 1.9059x; 1.2082x over previous
#include <cuda_runtime.h>
#include <cuda_fp16.h>
#include <cstdint>

// Problem constants: B=4, C=192, S=64, L=512
#define Bx 4
#define Cc 192
#define Ss 64
#define Ll 512
#define SL (Ss*Ll)            // 32768
#define CSL ((size_t)Cc*SL)   // 6291456

#define TL 64                 // l-tile per block (occ=2)

// W packing: per 64-k chunk, [hi image][lo image]; each image 192 rows x 72 halves (64 data + 8 pad)
#define WPITCH 72
#define HIMG_E (Cc*WPITCH)        // 13824 elems
#define CHUNK_E (2*HIMG_E)        // 27648 elems
#define CHUNK_B (CHUNK_E*2)       // 55296 bytes
#define HIMG_B (HIMG_E*2)         // 27648 bytes

__device__ __align__(16) __half g_wvpack[3*CHUNK_E];
__device__ __align__(16) __half g_wopack[3*CHUNK_E];
__device__ float g_ctx[Bx*Ss*Cc];

// X smem: [k=192 rows][l=64], pitch 72 halves (64 data + 8 pad), single fp16 image
#define XPITCH 72

// dynamic smem layout (bytes)
#define SM_W    0
#define SM_X    CHUNK_B                       // 55296
#define SM_CTX  (SM_X + Cc*XPITCH*2)          // 82944
#define SM_BV   (SM_CTX + Cc*4)
#define SM_BO   (SM_BV + Cc*4)
#define DSMEM_BYTES (SM_BO + Cc*4)            // 85248

// ---------------- PTX helpers (base sm_103 target only) ----------------
__device__ __forceinline__ uint32_t smem_u32(const void* p){
    return (uint32_t)__cvta_generic_to_shared(p);
}
#define MBAR_INIT(a, n)  asm volatile("mbarrier.init.shared.b64 [%0], %1;" :: "r"(a), "r"(n) : "memory")
#define MBAR_EXPECT(a, n) asm volatile("mbarrier.arrive.expect_tx.shared.b64 _, [%0], %1;" :: "r"(a), "r"(n) : "memory")
// Bounded wait: protocol bug => wrong answer, never a hang.
#define MBAR_WAIT(a, ph) do { \
    uint32_t _m = (a); uint32_t _p = (ph); uint32_t _done = 0; \
    for (int _i = 0; _i < 2000000 && !_done; _i++){ \
        asm volatile("{\n\t.reg .pred p;\n\t" \
            "mbarrier.try_wait.parity.shared.b64 p, [%1], %2;\n\t" \
            "selp.b32 %0, 1, 0, p;\n\t}" : "=r"(_done) : "r"(_m), "r"(_p) : "memory"); \
    } } while(0)
#define BULK_CP(dst, src, bytes, mbar) \
    asm volatile("cp.async.bulk.shared::cta.global.mbarrier::complete_tx::bytes [%0], [%1], %2, [%3];" \
        :: "r"(dst), "l"(src), "r"(bytes), "r"(mbar) : "memory")
#define FENCE_ASYNC() asm volatile("fence.proxy.async.shared::cta;" ::: "memory")

__device__ __forceinline__ void ldsm4(uint32_t r[4], uint32_t a){
    asm volatile("ldmatrix.sync.aligned.m8n8.x4.shared.b16 {%0,%1,%2,%3}, [%4];"
        : "=r"(r[0]), "=r"(r[1]), "=r"(r[2]), "=r"(r[3]) : "r"(a));
}
__device__ __forceinline__ void ldsm4t(uint32_t r[4], uint32_t a){
    asm volatile("ldmatrix.sync.aligned.m8n8.x4.trans.shared.b16 {%0,%1,%2,%3}, [%4];"
        : "=r"(r[0]), "=r"(r[1]), "=r"(r[2]), "=r"(r[3]) : "r"(a));
}
__device__ __forceinline__ void mma16816(float d[4], const uint32_t a[4], uint32_t b0, uint32_t b1){
    asm volatile("mma.sync.aligned.m16n8k16.row.col.f32.f16.f16.f32 "
        "{%0,%1,%2,%3}, {%4,%5,%6,%7}, {%8,%9}, {%0,%1,%2,%3};"
        : "+f"(d[0]), "+f"(d[1]), "+f"(d[2]), "+f"(d[3])
        : "r"(a[0]), "r"(a[1]), "r"(a[2]), "r"(a[3]), "r"(b0), "r"(b1));
}
__device__ __forceinline__ uint32_t pack_h2(float x, float y){
    __half a = __float2half(x), b = __float2half(y);
    return ((uint32_t)__half_as_ushort(b) << 16) | (uint32_t)__half_as_ushort(a);
}

// ---------------- K1: weight pack (blocks 0..143) + q-dot/softmax/key-sum/context ----------------
__global__ void __launch_bounds__(256) k_stage1(
    const float* __restrict__ query, const float* __restrict__ key,
    const float* __restrict__ ipw,   const float* __restrict__ ipb,
    const float* __restrict__ opw)
{
    __shared__ float wq_s[Cc];
    __shared__ float sc[Ll];
    __shared__ float kb_s[Cc];
    __shared__ float red[8];
    __shared__ float bcast;

    int tid = threadIdx.x;
    int bs  = blockIdx.x;
    int b = bs >> 6, s = bs & 63;
    int warp = tid >> 5, lane = tid & 31;

    // ---- merged weight pack: fp16 hi/lo, chunked [n][k] pitch-72 ----
    if (bs < 144){
        int i = bs*256 + tid;                 // covers 144*256 = 36864 = Cc*Cc
        int n = i / Cc, k = i % Cc;
        int kc = k >> 6, kk = k & 63;
        int off = kc*CHUNK_E + n*WPITCH + kk;
        {
            float w = ipw[(size_t)(1 + Cc + n)*Cc + k];      // wv[n][k]
            __half hi = __float2half(w);
            __half lo = __float2half(w - __half2float(hi));
            g_wvpack[off]          = hi;
            g_wvpack[off + HIMG_E] = lo;
        }
        {
            float w = opw[(size_t)n*Cc + k];                  // wo[n][k]
            __half hi = __float2half(w);
            __half lo = __float2half(w - __half2float(hi));
            g_wopack[off]          = hi;
            g_wopack[off + HIMG_E] = lo;
        }
    }

    if (tid < Cc) wq_s[tid] = ipw[tid];
    __syncthreads();

    const float* qb = query + (size_t)b*CSL + (size_t)s*Ll;
    float q0 = ipb[0], q1 = ipb[0];
    #pragma unroll 4
    for (int c = 0; c < Cc; c++){
        float w = wq_s[c];
        q0 = fmaf(w, qb[(size_t)c*SL + tid      ], q0);
        q1 = fmaf(w, qb[(size_t)c*SL + tid + 256], q1);
    }

    float m = fmaxf(q0, q1);
    #pragma unroll
    for (int o = 16; o; o >>= 1) m = fmaxf(m, __shfl_xor_sync(0xffffffffu, m, o));
    if (!lane) red[warp] = m;
    __syncthreads();
    if (tid == 0){ float mm = red[0]; for (int i = 1; i < 8; i++) mm = fmaxf(mm, red[i]); bcast = mm; }
    __syncthreads();
    float M = bcast;
    float e0 = expf(q0 - M), e1 = expf(q1 - M);
    float sum = e0 + e1;
    #pragma unroll
    for (int o = 16; o; o >>= 1) sum += __shfl_xor_sync(0xffffffffu, sum, o);
    __syncthreads();
    if (!lane) red[warp] = sum;
    __syncthreads();
    if (tid == 0){ float ss = 0.f; for (int i = 0; i < 8; i++) ss += red[i]; bcast = 1.f/ss; }
    __syncthreads();
    float inv = bcast;
    sc[tid]       = e0 * inv;
    sc[tid + 256] = e1 * inv;
    __syncthreads();

    const float* kbase = key + (size_t)b*CSL + (size_t)s*Ll;
    for (int c = warp; c < Cc; c += 8){
        const float* row = kbase + (size_t)c*SL;
        float a = 0.f;
        #pragma unroll 4
        for (int j = lane; j < Ll; j += 32) a = fmaf(row[j], sc[j], a);
        #pragma unroll
        for (int o = 16; o; o >>= 1) a += __shfl_xor_sync(0xffffffffu, a, o);
        if (!lane) kb_s[c] = a;
    }
    __syncthreads();

    if (tid < Cc){
        const float* wkr = ipw + (size_t)(1 + tid)*Cc;
        float a = ipb[1 + tid];
        #pragma unroll 4
        for (int j = 0; j < Cc; j++) a = fmaf(wkr[j], kb_s[j], a);
        g_ctx[(size_t)bs*Cc + tid] = a;
    }
}

// ---------------- K2: mma.sync fp16 2-product, fused v-proj -> relu*ctx -> out-proj ----------------
// 256 threads, 8 warps: (wid&3) -> n rows [48*(wid&3), +48) as 3 m16 tiles,
// (wid>>2) -> l cols [32*(wid>>2), +32) as 4 n8 tiles. D[n][l]. A=W (ldsm), B=X (ldsm.trans).
// 2-product: D = Whi*Xh + Wlo*Xh  (X truncated to fp16; dropped term ~2^-12 relative)
__global__ void __launch_bounds__(256, 2) k_main(
    const float* __restrict__ value,
    const float* __restrict__ ipb, const float* __restrict__ opb,
    float* __restrict__ out)
{
    extern __shared__ char dsm[];
    __shared__ __align__(8) unsigned long long s_mb;

    float* ctx_s = (float*)(dsm + SM_CTX);
    float* bv_s  = (float*)(dsm + SM_BV);
    float* bo_s  = (float*)(dsm + SM_BO);

    const uint32_t base = smem_u32(dsm);
    const uint32_t mb = smem_u32(&s_mb);

    int tid = threadIdx.x;
    int lane = tid & 31, wid = tid >> 5;
    int blk = blockIdx.x;
    int lt = blk & 7;
    int bs = blk >> 3;
    int b = bs >> 6, s = bs & 63;
    int l0t = lt * TL;

    // kick off W chunk 0 (GEMM1 = wv)
    if (tid == 0){
        MBAR_INIT(mb, 1);
        FENCE_ASYNC();
        MBAR_EXPECT(mb, CHUNK_B);
        BULK_CP(base + SM_W, (const char*)g_wvpack, CHUNK_B, mb);
    }

    for (int i = tid; i < Cc; i += 256){
        ctx_s[i] = g_ctx[(size_t)bs*Cc + i];
        bv_s[i]  = ipb[1 + Cc + i];
        bo_s[i]  = opb[i];
    }

    // ---- load value tile [192 c][64 l] fp32 -> fp16 X [k][l] pitch 72 ----
    {
        const float* vb = value + (size_t)b*CSL + (size_t)s*Ll + l0t;
        char* x = dsm + SM_X;
        #pragma unroll
        for (int it = 0; it < 12; it++){
            int f = tid + 256*it;            // 3072 float4 total
            int row = f >> 4, col = f & 15;  // col in float4 units
            float4 v = *(const float4*)(vb + (size_t)row*SL + (col << 2));
            uint2 hp;
            hp.x = pack_h2(v.x, v.y);
            hp.y = pack_h2(v.z, v.w);
            *(uint2*)(x + row*(XPITCH*2) + (col << 3)) = hp;
        }
    }
    __syncthreads();

    // warp tiling
    int m0  = (wid & 3) * 48;
    int lw0 = (wid >> 2) * 32;
    int g = lane >> 2, t = lane & 3;
    int lmr = (lane & 7) | (((lane >> 3) & 1) << 3);  // ldmatrix row within 16
    int lmc = (lane >> 4) << 3;                        // 0 or 8

    float d[3][4][4];
    #pragma unroll
    for (int a = 0; a < 3; a++)
        #pragma unroll
        for (int nt = 0; nt < 4; nt++)
            #pragma unroll
            for (int q = 0; q < 4; q++) d[a][nt][q] = 0.f;

    const uint32_t x_b = base + SM_X;
    const uint32_t w_b = base + SM_W;

    for (int ci = 0; ci < 6; ci++){
        if (ci == 3){
            // ---- epilogue 1: t = relu(v+bv)*ctx -> fp16 back into X smem ----
            #pragma unroll
            for (int mt = 0; mt < 3; mt++){
                #pragma unroll
                for (int nt = 0; nt < 4; nt++){
                    int o0 = m0 + mt*16 + g;
                    int l  = lw0 + nt*8 + t*2;
                    #pragma unroll
                    for (int h = 0; h < 2; h++){
                        int o = o0 + h*8;
                        float v0 = fmaxf(d[mt][nt][2*h]     + bv_s[o], 0.f) * ctx_s[o];
                        float v1 = fmaxf(d[mt][nt][2*h + 1] + bv_s[o], 0.f) * ctx_s[o];
                        *(uint32_t*)(dsm + SM_X + o*(XPITCH*2) + l*2) = pack_h2(v0, v1);
                    }
                }
            }
            #pragma unroll
            for (int a = 0; a < 3; a++)
                #pragma unroll
                for (int nt = 0; nt < 4; nt++)
                    #pragma unroll
                    for (int q = 0; q < 4; q++) d[a][nt][q] = 0.f;
            __syncthreads();
        }

        MBAR_WAIT(mb, ci & 1);

        int kc64 = (ci < 3 ? ci : ci - 3) * 64;

        #pragma unroll
        for (int ks = 0; ks < 4; ks++){
            // A fragments (weights), hi and lo images
            uint32_t Ah[3][4], Al[3][4];
            #pragma unroll
            for (int mt = 0; mt < 3; mt++){
                uint32_t arow = (uint32_t)((m0 + mt*16 + lmr)*WPITCH + ks*16 + lmc) * 2u;
                ldsm4(Ah[mt], w_b + arow);
                ldsm4(Al[mt], w_b + HIMG_B + arow);
            }
            int kg = kc64 + ks*16;
            #pragma unroll
            for (int ntp = 0; ntp < 2; ntp++){
                uint32_t boff = (uint32_t)((kg + lmr)*XPITCH + lw0 + ntp*16 + lmc) * 2u;
                uint32_t Bh[4];
                ldsm4t(Bh, x_b + boff);
                #pragma unroll
                for (int mt = 0; mt < 3; mt++){
                    mma16816(d[mt][ntp*2],     Ah[mt], Bh[0], Bh[1]);
                    mma16816(d[mt][ntp*2],     Al[mt], Bh[0], Bh[1]);
                    mma16816(d[mt][ntp*2 + 1], Ah[mt], Bh[2], Bh[3]);
                    mma16816(d[mt][ntp*2 + 1], Al[mt], Bh[2], Bh[3]);
                }
            }
        }
        __syncthreads();   // all warps done with this W buffer

        if (tid == 0 && ci < 5){
            int nc = ci + 1;
            const char* src = (nc < 3) ? ((const char*)g_wvpack + nc*CHUNK_B)
                                       : ((const char*)g_wopack + (nc - 3)*CHUNK_B);
            MBAR_EXPECT(mb, CHUNK_B);
            BULK_CP(base + SM_W, src, CHUNK_B, mb);
        }
    }

    // ---- epilogue 2: + bo, store to out [o][l] ----
    float* ob = out + (size_t)b*CSL + (size_t)s*Ll + l0t;
    #pragma unroll
    for (int mt = 0; mt < 3; mt++){
        #pragma unroll
        for (int nt = 0; nt < 4; nt++){
            int o0 = m0 + mt*16 + g;
            int l  = lw0 + nt*8 + t*2;
            #pragma unroll
            for (int h = 0; h < 2; h++){
                int o = o0 + h*8;
                float2 r;
                r.x = d[mt][nt][2*h]     + bo_s[o];
                r.y = d[mt][nt][2*h + 1] + bo_s[o];
                *(float2*)(ob + (size_t)o*SL + l) = r;
            }
        }
    }
}

extern "C" void kernel_launch(void* const* d_in, const int* in_sizes, int n_in,
                              void* d_out, int out_size)
{
    const float* query = (const float*)d_in[0];
    const float* key   = (const float*)d_in[1];
    const float* value = (const float*)d_in[2];
    const float* ipw   = (const float*)d_in[3];
    const float* ipb   = (const float*)d_in[4];
    const float* opw   = (const float*)d_in[5];
    const float* opb   = (const float*)d_in[6];
    float* out = (float*)d_out;

    cudaFuncSetAttribute(k_main, cudaFuncAttributeMaxDynamicSharedMemorySize, DSMEM_BYTES);

    k_stage1<<<Bx*Ss, 256>>>(query, key, ipw, ipb, opw);
    k_main<<<Bx*Ss*(Ll/TL), 256, DSMEM_BYTES>>>(value, ipb, opb, out);
}

// round 9
// speedup vs baseline: 2.4011x; 1.2598x over previous
#include <cuda_runtime.h>
#include <cuda_fp16.h>
#include <cstdint>

// Problem constants: B=4, C=192, S=64, L=512
#define Bx 4
#define Cc 192
#define Ss 64
#define Ll 512
#define SL (Ss*Ll)            // 32768
#define CSL ((size_t)Cc*SL)   // 6291456

#define TL 64                 // l-tile per block

// W packing: per 32-k chunk, [hi image][lo image]; each image 192 rows x 40 halves (32 data + 8 pad)
#define WPITCH 40
#define HIMG_E (Cc*WPITCH)        // 7680 elems
#define CHUNK_E (2*HIMG_E)        // 15360 elems
#define CHUNK_B (CHUNK_E*2)       // 30720 bytes
#define HIMG_B (HIMG_E*2)         // 15360 bytes
// unified: chunks 0..5 = wv (k 0..191), chunks 6..11 = wo
#define NCHUNK 12

__device__ __align__(16) __half g_wpack[NCHUNK*CHUNK_E];
__device__ float g_ctx[Bx*Ss*Cc];      // ctx[(b*64+s)*192 + c]
__device__ float g_sc[Bx*Ss*Ll];       // softmax scores
__device__ float g_kbar[Bx*Ss*Cc];     // weighted key sums

// X smem: [k=192 rows][l=64], pitch 72 halves (64 data + 8 pad), single fp16 image
#define XPITCH 72

// dynamic smem layout (bytes)
#define SM_W0   0
#define SM_W1   CHUNK_B                       // 30720
#define SM_X    (2*CHUNK_B)                   // 61440
#define SM_CTX  (SM_X + Cc*XPITCH*2)          // 89088
#define SM_BV   (SM_CTX + Cc*4)
#define SM_BO   (SM_BV + Cc*4)
#define DSMEM_BYTES (SM_BO + Cc*4)            // 91392

// ---------------- PTX helpers (base sm_103 target only) ----------------
__device__ __forceinline__ uint32_t smem_u32(const void* p){
    return (uint32_t)__cvta_generic_to_shared(p);
}
#define MBAR_INIT(a, n)  asm volatile("mbarrier.init.shared.b64 [%0], %1;" :: "r"(a), "r"(n) : "memory")
#define MBAR_EXPECT(a, n) asm volatile("mbarrier.arrive.expect_tx.shared.b64 _, [%0], %1;" :: "r"(a), "r"(n) : "memory")
// Bounded wait: protocol bug => wrong answer, never a hang.
#define MBAR_WAIT(a, ph) do { \
    uint32_t _m = (a); uint32_t _p = (ph); uint32_t _done = 0; \
    for (int _i = 0; _i < 2000000 && !_done; _i++){ \
        asm volatile("{\n\t.reg .pred p;\n\t" \
            "mbarrier.try_wait.parity.shared.b64 p, [%1], %2;\n\t" \
            "selp.b32 %0, 1, 0, p;\n\t}" : "=r"(_done) : "r"(_m), "r"(_p) : "memory"); \
    } } while(0)
#define BULK_CP(dst, src, bytes, mbar) \
    asm volatile("cp.async.bulk.shared::cta.global.mbarrier::complete_tx::bytes [%0], [%1], %2, [%3];" \
        :: "r"(dst), "l"(src), "r"(bytes), "r"(mbar) : "memory")
#define FENCE_ASYNC() asm volatile("fence.proxy.async.shared::cta;" ::: "memory")

__device__ __forceinline__ void ldsm4(uint32_t r[4], uint32_t a){
    asm volatile("ldmatrix.sync.aligned.m8n8.x4.shared.b16 {%0,%1,%2,%3}, [%4];"
        : "=r"(r[0]), "=r"(r[1]), "=r"(r[2]), "=r"(r[3]) : "r"(a));
}
__device__ __forceinline__ void ldsm4t(uint32_t r[4], uint32_t a){
    asm volatile("ldmatrix.sync.aligned.m8n8.x4.trans.shared.b16 {%0,%1,%2,%3}, [%4];"
        : "=r"(r[0]), "=r"(r[1]), "=r"(r[2]), "=r"(r[3]) : "r"(a));
}
__device__ __forceinline__ void mma16816(float d[4], const uint32_t a[4], uint32_t b0, uint32_t b1){
    asm volatile("mma.sync.aligned.m16n8k16.row.col.f32.f16.f16.f32 "
        "{%0,%1,%2,%3}, {%4,%5,%6,%7}, {%8,%9}, {%0,%1,%2,%3};"
        : "+f"(d[0]), "+f"(d[1]), "+f"(d[2]), "+f"(d[3])
        : "r"(a[0]), "r"(a[1]), "r"(a[2]), "r"(a[3]), "r"(b0), "r"(b1));
}
__device__ __forceinline__ uint32_t pack_h2(float x, float y){
    __half a = __float2half(x), b = __float2half(y);
    return ((uint32_t)__half_as_ushort(b) << 16) | (uint32_t)__half_as_ushort(a);
}

// ---------------- K1a: weight pack (blocks 0..143) + q-dot + softmax -> scores ----------------
__global__ void __launch_bounds__(256) k_q(
    const float* __restrict__ query, const float* __restrict__ ipw,
    const float* __restrict__ ipb,   const float* __restrict__ opw)
{
    __shared__ float wq_s[Cc];
    __shared__ float red[8];
    __shared__ float bcast;

    int tid = threadIdx.x;
    int bs  = blockIdx.x;
    int b = bs >> 6, s = bs & 63;
    int warp = tid >> 5, lane = tid & 31;

    // ---- merged weight pack: fp16 hi/lo, 32-k chunks [n][k] pitch-40 ----
    if (bs < 144){
        int i = bs*256 + tid;                 // 144*256 = 36864 = Cc*Cc
        int n = i / Cc, k = i % Cc;
        int kc = k >> 5, kk = k & 31;
        {
            float w = ipw[(size_t)(1 + Cc + n)*Cc + k];      // wv[n][k]
            __half hi = __float2half(w);
            __half lo = __float2half(w - __half2float(hi));
            int off = kc*CHUNK_E + n*WPITCH + kk;
            g_wpack[off]          = hi;
            g_wpack[off + HIMG_E] = lo;
        }
        {
            float w = opw[(size_t)n*Cc + k];                  // wo[n][k]
            __half hi = __float2half(w);
            __half lo = __float2half(w - __half2float(hi));
            int off = (6 + kc)*CHUNK_E + n*WPITCH + kk;
            g_wpack[off]          = hi;
            g_wpack[off + HIMG_E] = lo;
        }
    }

    if (tid < Cc) wq_s[tid] = ipw[tid];
    __syncthreads();

    // q for l = 2*tid, 2*tid+1 (float2 loads, deep unroll for MLP)
    const float* qb = query + (size_t)b*CSL + (size_t)s*Ll + 2*tid;
    float q0 = ipb[0], q1 = ipb[0];
    #pragma unroll 8
    for (int c = 0; c < Cc; c++){
        float w = wq_s[c];
        float2 v = *(const float2*)(qb + (size_t)c*SL);
        q0 = fmaf(w, v.x, q0);
        q1 = fmaf(w, v.y, q1);
    }

    // softmax over 512
    float m = fmaxf(q0, q1);
    #pragma unroll
    for (int o = 16; o; o >>= 1) m = fmaxf(m, __shfl_xor_sync(0xffffffffu, m, o));
    if (!lane) red[warp] = m;
    __syncthreads();
    if (tid == 0){ float mm = red[0]; for (int i = 1; i < 8; i++) mm = fmaxf(mm, red[i]); bcast = mm; }
    __syncthreads();
    float M = bcast;
    float e0 = expf(q0 - M), e1 = expf(q1 - M);
    float sum = e0 + e1;
    #pragma unroll
    for (int o = 16; o; o >>= 1) sum += __shfl_xor_sync(0xffffffffu, sum, o);
    __syncthreads();
    if (!lane) red[warp] = sum;
    __syncthreads();
    if (tid == 0){ float ss = 0.f; for (int i = 0; i < 8; i++) ss += red[i]; bcast = 1.f/ss; }
    __syncthreads();
    float inv = bcast;
    float2 r; r.x = e0*inv; r.y = e1*inv;
    *(float2*)(g_sc + (size_t)bs*Ll + 2*tid) = r;
}

// ---------------- K1b: kbar[c] = sum_l key[b,c,s,l]*sc[l] ----------------
// grid (256, 6); each block: 32 c-rows, 4 per warp; float2 loads, 5 streams in flight.
__global__ void __launch_bounds__(256) k_kbar(const float* __restrict__ key)
{
    int tid = threadIdx.x;
    int bs = blockIdx.x, cg = blockIdx.y;
    int b = bs >> 6, s = bs & 63;
    int w = tid >> 5, lane = tid & 31;
    int c0 = cg*32 + w*4;

    const float* sc = g_sc + (size_t)bs*Ll + 2*lane;
    const float* k0 = key + (size_t)b*CSL + (size_t)s*Ll + (size_t)c0*SL + 2*lane;

    float a0 = 0.f, a1 = 0.f, a2 = 0.f, a3 = 0.f;
    #pragma unroll
    for (int j = 0; j < Ll; j += 64){
        float2 s2 = *(const float2*)(sc + j);
        float2 r0 = *(const float2*)(k0 + j);
        float2 r1 = *(const float2*)(k0 + SL + j);
        float2 r2 = *(const float2*)(k0 + 2*SL + j);
        float2 r3 = *(const float2*)(k0 + 3*SL + j);
        a0 = fmaf(r0.x, s2.x, fmaf(r0.y, s2.y, a0));
        a1 = fmaf(r1.x, s2.x, fmaf(r1.y, s2.y, a1));
        a2 = fmaf(r2.x, s2.x, fmaf(r2.y, s2.y, a2));
        a3 = fmaf(r3.x, s2.x, fmaf(r3.y, s2.y, a3));
    }
    #pragma unroll
    for (int o = 16; o; o >>= 1){
        a0 += __shfl_xor_sync(0xffffffffu, a0, o);
        a1 += __shfl_xor_sync(0xffffffffu, a1, o);
        a2 += __shfl_xor_sync(0xffffffffu, a2, o);
        a3 += __shfl_xor_sync(0xffffffffu, a3, o);
    }
    if (!lane){
        float* kb = g_kbar + (size_t)bs*Cc + c0;
        kb[0] = a0; kb[1] = a1; kb[2] = a2; kb[3] = a3;
    }
}

// ---------------- K1c: ctx[c] = wk[c,:].kbar + bk[c] ----------------
__global__ void __launch_bounds__(192) k_ctx(
    const float* __restrict__ ipw, const float* __restrict__ ipb)
{
    __shared__ float kb_s[Cc];
    int tid = threadIdx.x;
    int bs = blockIdx.x;
    kb_s[tid] = g_kbar[(size_t)bs*Cc + tid];
    __syncthreads();
    const float* wkr = ipw + (size_t)(1 + tid)*Cc;
    float a = ipb[1 + tid];
    #pragma unroll 8
    for (int j = 0; j < Cc; j++) a = fmaf(wkr[j], kb_s[j], a);
    g_ctx[(size_t)bs*Cc + tid] = a;
}

// ---------------- K2: mma.sync fp16 2-product, double-buffered 32-k W chunks ----------------
// 256 threads, 8 warps: (wid&3) -> n rows [48*(wid&3), +48) as 3 m16 tiles,
// (wid>>2) -> l cols [32*(wid>>2), +32) as 4 n8 tiles. D[n][l]. A=W (ldsm), B=X (ldsm.trans).
__global__ void __launch_bounds__(256, 2) k_main(
    const float* __restrict__ value,
    const float* __restrict__ ipb, const float* __restrict__ opb,
    float* __restrict__ out)
{
    extern __shared__ char dsm[];
    __shared__ __align__(8) unsigned long long s_mb[2];

    float* ctx_s = (float*)(dsm + SM_CTX);
    float* bv_s  = (float*)(dsm + SM_BV);
    float* bo_s  = (float*)(dsm + SM_BO);

    const uint32_t base = smem_u32(dsm);
    const uint32_t mb0 = smem_u32(&s_mb[0]);
    const uint32_t mb1 = smem_u32(&s_mb[1]);

    int tid = threadIdx.x;
    int lane = tid & 31, wid = tid >> 5;
    int blk = blockIdx.x;
    int lt = blk & 7;
    int bs = blk >> 3;
    int b = bs >> 6, s = bs & 63;
    int l0t = lt * TL;

    // init + prefetch chunks 0,1
    if (tid == 0){
        MBAR_INIT(mb0, 1); MBAR_INIT(mb1, 1);
        FENCE_ASYNC();
        MBAR_EXPECT(mb0, CHUNK_B);
        BULK_CP(base + SM_W0, (const char*)g_wpack, CHUNK_B, mb0);
        MBAR_EXPECT(mb1, CHUNK_B);
        BULK_CP(base + SM_W1, (const char*)g_wpack + CHUNK_B, CHUNK_B, mb1);
    }

    for (int i = tid; i < Cc; i += 256){
        ctx_s[i] = g_ctx[(size_t)bs*Cc + i];
        bv_s[i]  = ipb[1 + Cc + i];
        bo_s[i]  = opb[i];
    }

    // ---- load value tile [192 c][64 l] fp32 -> fp16 X [k][l] pitch 72 ----
    {
        const float* vb = value + (size_t)b*CSL + (size_t)s*Ll + l0t;
        char* x = dsm + SM_X;
        #pragma unroll
        for (int it = 0; it < 12; it++){
            int f = tid + 256*it;            // 3072 float4 total
            int row = f >> 4, col = f & 15;  // col in float4 units
            float4 v = *(const float4*)(vb + (size_t)row*SL + (col << 2));
            uint2 hp;
            hp.x = pack_h2(v.x, v.y);
            hp.y = pack_h2(v.z, v.w);
            *(uint2*)(x + row*(XPITCH*2) + (col << 3)) = hp;
        }
    }
    __syncthreads();

    // warp tiling
    int m0  = (wid & 3) * 48;
    int lw0 = (wid >> 2) * 32;
    int g = lane >> 2, t = lane & 3;
    int lmr = (lane & 7) | (((lane >> 3) & 1) << 3);  // ldmatrix row within 16
    int lmc = (lane >> 4) << 3;                        // 0 or 8

    float d[3][4][4];
    #pragma unroll
    for (int a = 0; a < 3; a++)
        #pragma unroll
        for (int nt = 0; nt < 4; nt++)
            #pragma unroll
            for (int q = 0; q < 4; q++) d[a][nt][q] = 0.f;

    const uint32_t x_b = base + SM_X;

    for (int ci = 0; ci < NCHUNK; ci++){
        if (ci == 6){
            // ---- epilogue 1: t = relu(v+bv)*ctx -> fp16 back into X smem ----
            // (post-chunk-5 __syncthreads => all GEMM1 X reads done)
            #pragma unroll
            for (int mt = 0; mt < 3; mt++){
                #pragma unroll
                for (int nt = 0; nt < 4; nt++){
                    int o0 = m0 + mt*16 + g;
                    int l  = lw0 + nt*8 + t*2;
                    #pragma unroll
                    for (int h = 0; h < 2; h++){
                        int o = o0 + h*8;
                        float v0 = fmaxf(d[mt][nt][2*h]     + bv_s[o], 0.f) * ctx_s[o];
                        float v1 = fmaxf(d[mt][nt][2*h + 1] + bv_s[o], 0.f) * ctx_s[o];
                        *(uint32_t*)(dsm + SM_X + o*(XPITCH*2) + l*2) = pack_h2(v0, v1);
                    }
                }
            }
            #pragma unroll
            for (int a = 0; a < 3; a++)
                #pragma unroll
                for (int nt = 0; nt < 4; nt++)
                    #pragma unroll
                    for (int q = 0; q < 4; q++) d[a][nt][q] = 0.f;
            __syncthreads();
        }

        int buf = ci & 1;
        MBAR_WAIT(buf ? mb1 : mb0, (ci >> 1) & 1);
        uint32_t w_b = base + (buf ? SM_W1 : SM_W0);
        int kc32 = (ci < 6 ? ci : ci - 6) * 32;

        #pragma unroll
        for (int ks = 0; ks < 2; ks++){
            // A fragments (weights), hi and lo images
            uint32_t Ah[3][4], Al[3][4];
            #pragma unroll
            for (int mt = 0; mt < 3; mt++){
                uint32_t arow = (uint32_t)((m0 + mt*16 + lmr)*WPITCH + ks*16 + lmc) * 2u;
                ldsm4(Ah[mt], w_b + arow);
                ldsm4(Al[mt], w_b + HIMG_B + arow);
            }
            int kg = kc32 + ks*16;
            #pragma unroll
            for (int ntp = 0; ntp < 2; ntp++){
                uint32_t boff = (uint32_t)((kg + lmr)*XPITCH + lw0 + ntp*16 + lmc) * 2u;
                uint32_t Bh[4];
                ldsm4t(Bh, x_b + boff);
                #pragma unroll
                for (int mt = 0; mt < 3; mt++){
                    mma16816(d[mt][ntp*2],     Ah[mt], Bh[0], Bh[1]);
                    mma16816(d[mt][ntp*2],     Al[mt], Bh[0], Bh[1]);
                    mma16816(d[mt][ntp*2 + 1], Ah[mt], Bh[2], Bh[3]);
                    mma16816(d[mt][ntp*2 + 1], Al[mt], Bh[2], Bh[3]);
                }
            }
        }
        __syncthreads();   // all warps done reading this W buffer

        if (tid == 0 && ci < NCHUNK - 2){
            int nc = ci + 2;
            uint32_t mb = (nc & 1) ? mb1 : mb0;
            MBAR_EXPECT(mb, CHUNK_B);
            BULK_CP(base + (nc & 1 ? SM_W1 : SM_W0),
                    (const char*)g_wpack + (size_t)nc*CHUNK_B, CHUNK_B, mb);
        }
    }

    // ---- epilogue 2: + bo, store to out [o][l] ----
    float* ob = out + (size_t)b*CSL + (size_t)s*Ll + l0t;
    #pragma unroll
    for (int mt = 0; mt < 3; mt++){
        #pragma unroll
        for (int nt = 0; nt < 4; nt++){
            int o0 = m0 + mt*16 + g;
            int l  = lw0 + nt*8 + t*2;
            #pragma unroll
            for (int h = 0; h < 2; h++){
                int o = o0 + h*8;
                float2 r;
                r.x = d[mt][nt][2*h]     + bo_s[o];
                r.y = d[mt][nt][2*h + 1] + bo_s[o];
                *(float2*)(ob + (size_t)o*SL + l) = r;
            }
        }
    }
}

extern "C" void kernel_launch(void* const* d_in, const int* in_sizes, int n_in,
                              void* d_out, int out_size)
{
    const float* query = (const float*)d_in[0];
    const float* key   = (const float*)d_in[1];
    const float* value = (const float*)d_in[2];
    const float* ipw   = (const float*)d_in[3];
    const float* ipb   = (const float*)d_in[4];
    const float* opw   = (const float*)d_in[5];
    const float* opb   = (const float*)d_in[6];
    float* out = (float*)d_out;

    cudaFuncSetAttribute(k_main, cudaFuncAttributeMaxDynamicSharedMemorySize, DSMEM_BYTES);

    k_q<<<Bx*Ss, 256>>>(query, ipw, ipb, opw);
    dim3 kb_grid(Bx*Ss, Cc/32);
    k_kbar<<<kb_grid, 256>>>(key);
    k_ctx<<<Bx*Ss, 192>>>(ipw, ipb);
    k_main<<<Bx*Ss*(Ll/TL), 256, DSMEM_BYTES>>>(value, ipb, opb, out);
}

// round 11
// speedup vs baseline: 2.4026x; 1.0006x over previous
#include <cuda_runtime.h>
#include <cuda_fp16.h>
#include <cstdint>

// Problem constants: B=4, C=192, S=64, L=512
#define Bx 4
#define Cc 192
#define Ss 64
#define Ll 512
#define SL (Ss*Ll)            // 32768
#define CSL ((size_t)Cc*SL)   // 6291456

#define TL 64                 // l-tile per block

// W packing: per 32-k chunk, [hi image][lo image]; each image 192 rows x 40 halves (32 data + 8 pad)
#define WPITCH 40
#define HIMG_E (Cc*WPITCH)        // 7680 elems
#define CHUNK_E (2*HIMG_E)        // 15360 elems
#define CHUNK_B (CHUNK_E*2)       // 30720 bytes
#define HIMG_B (HIMG_E*2)         // 15360 bytes
// unified: chunks 0..5 = wv (k 0..191), chunks 6..11 = wo
#define NCHUNK 12

__device__ __align__(16) __half g_wpack[NCHUNK*CHUNK_E];
__device__ float g_ctx[Bx*Ss*Cc];      // ctx[(b*64+s)*192 + c]
__device__ float g_sc[Bx*Ss*Ll];       // softmax scores

// X smem: [k=192 rows][l=64], pitch 72 halves (64 data + 8 pad), single fp16 image
#define XPITCH 72

// dynamic smem layout (bytes)
#define SM_W0   0
#define SM_W1   CHUNK_B                       // 30720
#define SM_X    (2*CHUNK_B)                   // 61440
#define SM_CTX  (SM_X + Cc*XPITCH*2)          // 89088
#define SM_BV   (SM_CTX + Cc*4)
#define SM_BO   (SM_BV + Cc*4)
#define DSMEM_BYTES (SM_BO + Cc*4)            // 91392

// ---------------- PTX helpers (base sm_103 target only) ----------------
__device__ __forceinline__ uint32_t smem_u32(const void* p){
    return (uint32_t)__cvta_generic_to_shared(p);
}
#define MBAR_INIT(a, n)  asm volatile("mbarrier.init.shared.b64 [%0], %1;" :: "r"(a), "r"(n) : "memory")
#define MBAR_EXPECT(a, n) asm volatile("mbarrier.arrive.expect_tx.shared.b64 _, [%0], %1;" :: "r"(a), "r"(n) : "memory")
// Bounded wait: protocol bug => wrong answer, never a hang.
#define MBAR_WAIT(a, ph) do { \
    uint32_t _m = (a); uint32_t _p = (ph); uint32_t _done = 0; \
    for (int _i = 0; _i < 2000000 && !_done; _i++){ \
        asm volatile("{\n\t.reg .pred p;\n\t" \
            "mbarrier.try_wait.parity.shared.b64 p, [%1], %2;\n\t" \
            "selp.b32 %0, 1, 0, p;\n\t}" : "=r"(_done) : "r"(_m), "r"(_p) : "memory"); \
    } } while(0)
#define BULK_CP(dst, src, bytes, mbar) \
    asm volatile("cp.async.bulk.shared::cta.global.mbarrier::complete_tx::bytes [%0], [%1], %2, [%3];" \
        :: "r"(dst), "l"(src), "r"(bytes), "r"(mbar) : "memory")
#define FENCE_ASYNC() asm volatile("fence.proxy.async.shared::cta;" ::: "memory")

__device__ __forceinline__ void ldsm4(uint32_t r[4], uint32_t a){
    asm volatile("ldmatrix.sync.aligned.m8n8.x4.shared.b16 {%0,%1,%2,%3}, [%4];"
        : "=r"(r[0]), "=r"(r[1]), "=r"(r[2]), "=r"(r[3]) : "r"(a));
}
__device__ __forceinline__ void ldsm4t(uint32_t r[4], uint32_t a){
    asm volatile("ldmatrix.sync.aligned.m8n8.x4.trans.shared.b16 {%0,%1,%2,%3}, [%4];"
        : "=r"(r[0]), "=r"(r[1]), "=r"(r[2]), "=r"(r[3]) : "r"(a));
}
__device__ __forceinline__ void mma16816(float d[4], const uint32_t a[4], uint32_t b0, uint32_t b1){
    asm volatile("mma.sync.aligned.m16n8k16.row.col.f32.f16.f16.f32 "
        "{%0,%1,%2,%3}, {%4,%5,%6,%7}, {%8,%9}, {%0,%1,%2,%3};"
        : "+f"(d[0]), "+f"(d[1]), "+f"(d[2]), "+f"(d[3])
        : "r"(a[0]), "r"(a[1]), "r"(a[2]), "r"(a[3]), "r"(b0), "r"(b1));
}
__device__ __forceinline__ uint32_t pack_h2(float x, float y){
    __half a = __float2half(x), b = __float2half(y);
    return ((uint32_t)__half_as_ushort(b) << 16) | (uint32_t)__half_as_ushort(a);
}

// ---------------- K1a: weight pack (blocks 0..143) + q-dot + softmax -> scores ----------------
__global__ void __launch_bounds__(256) k_q(
    const float* __restrict__ query, const float* __restrict__ ipw,
    const float* __restrict__ ipb,   const float* __restrict__ opw)
{
    __shared__ float wq_s[Cc];
    __shared__ float red[8];
    __shared__ float bcast;

    int tid = threadIdx.x;
    int bs  = blockIdx.x;
    int b = bs >> 6, s = bs & 63;
    int warp = tid >> 5, lane = tid & 31;

    // ---- merged weight pack: fp16 hi/lo, 32-k chunks [n][k] pitch-40 ----
    if (bs < 144){
        int i = bs*256 + tid;                 // 144*256 = 36864 = Cc*Cc
        int n = i / Cc, k = i % Cc;
        int kc = k >> 5, kk = k & 31;
        {
            float w = ipw[(size_t)(1 + Cc + n)*Cc + k];      // wv[n][k]
            __half hi = __float2half(w);
            __half lo = __float2half(w - __half2float(hi));
            int off = kc*CHUNK_E + n*WPITCH + kk;
            g_wpack[off]          = hi;
            g_wpack[off + HIMG_E] = lo;
        }
        {
            float w = opw[(size_t)n*Cc + k];                  // wo[n][k]
            __half hi = __float2half(w);
            __half lo = __float2half(w - __half2float(hi));
            int off = (6 + kc)*CHUNK_E + n*WPITCH + kk;
            g_wpack[off]          = hi;
            g_wpack[off + HIMG_E] = lo;
        }
    }

    if (tid < Cc) wq_s[tid] = ipw[tid];
    __syncthreads();

    // q for l = 2*tid, 2*tid+1 (float2 loads, deep unroll for MLP)
    const float* qb = query + (size_t)b*CSL + (size_t)s*Ll + 2*tid;
    float q0 = ipb[0], q1 = ipb[0];
    #pragma unroll 8
    for (int c = 0; c < Cc; c++){
        float w = wq_s[c];
        float2 v = *(const float2*)(qb + (size_t)c*SL);
        q0 = fmaf(w, v.x, q0);
        q1 = fmaf(w, v.y, q1);
    }

    // softmax over 512
    float m = fmaxf(q0, q1);
    #pragma unroll
    for (int o = 16; o; o >>= 1) m = fmaxf(m, __shfl_xor_sync(0xffffffffu, m, o));
    if (!lane) red[warp] = m;
    __syncthreads();
    if (tid == 0){ float mm = red[0]; for (int i = 1; i < 8; i++) mm = fmaxf(mm, red[i]); bcast = mm; }
    __syncthreads();
    float M = bcast;
    float e0 = expf(q0 - M), e1 = expf(q1 - M);
    float sum = e0 + e1;
    #pragma unroll
    for (int o = 16; o; o >>= 1) sum += __shfl_xor_sync(0xffffffffu, sum, o);
    __syncthreads();
    if (!lane) red[warp] = sum;
    __syncthreads();
    if (tid == 0){ float ss = 0.f; for (int i = 0; i < 8; i++) ss += red[i]; bcast = 1.f/ss; }
    __syncthreads();
    float inv = bcast;
    float2 r; r.x = e0*inv; r.y = e1*inv;
    *(float2*)(g_sc + (size_t)bs*Ll + 2*tid) = r;
}

// ---------------- K1b: fused kbar + ctx ----------------
// 256 blocks (one per bs), 512 threads (16 warps x 12 c-rows = 192 rows).
// Phase A: kbar[c] = sum_l key[b,c,s,l]*sc[l]  (scores staged in smem)
// Phase B: ctx[c] = wk[c,:].kbar + bk[c]       (kbar staged in smem)
__global__ void __launch_bounds__(512) k_kbar(
    const float* __restrict__ key,
    const float* __restrict__ ipw, const float* __restrict__ ipb)
{
    __shared__ float sc_s[Ll];
    __shared__ float kb_s[Cc];

    int tid = threadIdx.x;
    int bs = blockIdx.x;
    int b = bs >> 6, s = bs & 63;
    int w = tid >> 5, lane = tid & 31;

    sc_s[tid] = g_sc[(size_t)bs*Ll + tid];
    __syncthreads();

    // 12 rows per warp: c = w*12 + r
    const float* kbase = key + (size_t)b*CSL + (size_t)s*Ll + 2*lane;
    int c0 = w*12;
    float acc[12];
    #pragma unroll
    for (int r = 0; r < 12; r++) acc[r] = 0.f;

    #pragma unroll
    for (int j = 0; j < Ll; j += 64){
        float2 s2 = *(const float2*)(sc_s + 2*lane + j);
        #pragma unroll
        for (int r = 0; r < 12; r++){
            float2 kv = *(const float2*)(kbase + (size_t)(c0 + r)*SL + j);
            acc[r] = fmaf(kv.x, s2.x, fmaf(kv.y, s2.y, acc[r]));
        }
    }
    #pragma unroll
    for (int r = 0; r < 12; r++){
        float a = acc[r];
        #pragma unroll
        for (int o = 16; o; o >>= 1) a += __shfl_xor_sync(0xffffffffu, a, o);
        if (!lane) kb_s[c0 + r] = a;
    }
    __syncthreads();

    // ctx: threads 0..191
    if (tid < Cc){
        const float* wkr = ipw + (size_t)(1 + tid)*Cc;
        float a = ipb[1 + tid];
        #pragma unroll 8
        for (int j = 0; j < Cc; j++) a = fmaf(wkr[j], kb_s[j], a);
        g_ctx[(size_t)bs*Cc + tid] = a;
    }
}

// ---------------- K2: mma.sync fp16 2-product, double-buffered 32-k W chunks (R9-proven) ----------------
// 256 threads, 8 warps: (wid&3) -> n rows [48*(wid&3), +48) as 3 m16 tiles,
// (wid>>2) -> l cols [32*(wid>>2), +32) as 4 n8 tiles. D[n][l]. A=W (ldsm), B=X (ldsm.trans).
__global__ void __launch_bounds__(256, 2) k_main(
    const float* __restrict__ value,
    const float* __restrict__ ipb, const float* __restrict__ opb,
    float* __restrict__ out)
{
    extern __shared__ char dsm[];
    __shared__ __align__(8) unsigned long long s_mb[2];

    float* ctx_s = (float*)(dsm + SM_CTX);
    float* bv_s  = (float*)(dsm + SM_BV);
    float* bo_s  = (float*)(dsm + SM_BO);

    const uint32_t base = smem_u32(dsm);
    const uint32_t mb0 = smem_u32(&s_mb[0]);
    const uint32_t mb1 = smem_u32(&s_mb[1]);

    int tid = threadIdx.x;
    int lane = tid & 31, wid = tid >> 5;
    int blk = blockIdx.x;
    int lt = blk & 7;
    int bs = blk >> 3;
    int b = bs >> 6, s = bs & 63;
    int l0t = lt * TL;

    // init + prefetch chunks 0,1
    if (tid == 0){
        MBAR_INIT(mb0, 1); MBAR_INIT(mb1, 1);
        FENCE_ASYNC();
        MBAR_EXPECT(mb0, CHUNK_B);
        BULK_CP(base + SM_W0, (const char*)g_wpack, CHUNK_B, mb0);
        MBAR_EXPECT(mb1, CHUNK_B);
        BULK_CP(base + SM_W1, (const char*)g_wpack + CHUNK_B, CHUNK_B, mb1);
    }

    for (int i = tid; i < Cc; i += 256){
        ctx_s[i] = g_ctx[(size_t)bs*Cc + i];
        bv_s[i]  = ipb[1 + Cc + i];
        bo_s[i]  = opb[i];
    }

    // ---- load value tile [192 c][64 l] fp32 -> fp16 X [k][l] pitch 72 ----
    {
        const float* vb = value + (size_t)b*CSL + (size_t)s*Ll + l0t;
        char* x = dsm + SM_X;
        #pragma unroll
        for (int it = 0; it < 12; it++){
            int f = tid + 256*it;            // 3072 float4 total
            int row = f >> 4, col = f & 15;  // col in float4 units
            float4 v = *(const float4*)(vb + (size_t)row*SL + (col << 2));
            uint2 hp;
            hp.x = pack_h2(v.x, v.y);
            hp.y = pack_h2(v.z, v.w);
            *(uint2*)(x + row*(XPITCH*2) + (col << 3)) = hp;
        }
    }
    __syncthreads();

    // warp tiling
    int m0  = (wid & 3) * 48;
    int lw0 = (wid >> 2) * 32;
    int g = lane >> 2, t = lane & 3;
    int lmr = (lane & 7) | (((lane >> 3) & 1) << 3);  // ldmatrix row within 16
    int lmc = (lane >> 4) << 3;                        // 0 or 8

    float d[3][4][4];
    #pragma unroll
    for (int a = 0; a < 3; a++)
        #pragma unroll
        for (int nt = 0; nt < 4; nt++)
            #pragma unroll
            for (int q = 0; q < 4; q++) d[a][nt][q] = 0.f;

    const uint32_t x_b = base + SM_X;

    for (int ci = 0; ci < NCHUNK; ci++){
        if (ci == 6){
            // ---- epilogue 1: t = relu(v+bv)*ctx -> fp16 back into X smem ----
            // (post-chunk-5 __syncthreads => all GEMM1 X reads done)
            #pragma unroll
            for (int mt = 0; mt < 3; mt++){
                #pragma unroll
                for (int nt = 0; nt < 4; nt++){
                    int o0 = m0 + mt*16 + g;
                    int l  = lw0 + nt*8 + t*2;
                    #pragma unroll
                    for (int h = 0; h < 2; h++){
                        int o = o0 + h*8;
                        float v0 = fmaxf(d[mt][nt][2*h]     + bv_s[o], 0.f) * ctx_s[o];
                        float v1 = fmaxf(d[mt][nt][2*h + 1] + bv_s[o], 0.f) * ctx_s[o];
                        *(uint32_t*)(dsm + SM_X + o*(XPITCH*2) + l*2) = pack_h2(v0, v1);
                    }
                }
            }
            #pragma unroll
            for (int a = 0; a < 3; a++)
                #pragma unroll
                for (int nt = 0; nt < 4; nt++)
                    #pragma unroll
                    for (int q = 0; q < 4; q++) d[a][nt][q] = 0.f;
            __syncthreads();
        }

        int buf = ci & 1;
        MBAR_WAIT(buf ? mb1 : mb0, (ci >> 1) & 1);
        uint32_t w_b = base + (buf ? SM_W1 : SM_W0);
        int kc32 = (ci < 6 ? ci : ci - 6) * 32;

        #pragma unroll
        for (int ks = 0; ks < 2; ks++){
            // A fragments (weights), hi and lo images
            uint32_t Ah[3][4], Al[3][4];
            #pragma unroll
            for (int mt = 0; mt < 3; mt++){
                uint32_t arow = (uint32_t)((m0 + mt*16 + lmr)*WPITCH + ks*16 + lmc) * 2u;
                ldsm4(Ah[mt], w_b + arow);
                ldsm4(Al[mt], w_b + HIMG_B + arow);
            }
            int kg = kc32 + ks*16;
            #pragma unroll
            for (int ntp = 0; ntp < 2; ntp++){
                uint32_t boff = (uint32_t)((kg + lmr)*XPITCH + lw0 + ntp*16 + lmc) * 2u;
                uint32_t Bh[4];
                ldsm4t(Bh, x_b + boff);
                #pragma unroll
                for (int mt = 0; mt < 3; mt++){
                    mma16816(d[mt][ntp*2],     Ah[mt], Bh[0], Bh[1]);
                    mma16816(d[mt][ntp*2],     Al[mt], Bh[0], Bh[1]);
                    mma16816(d[mt][ntp*2 + 1], Ah[mt], Bh[2], Bh[3]);
                    mma16816(d[mt][ntp*2 + 1], Al[mt], Bh[2], Bh[3]);
                }
            }
        }
        __syncthreads();   // all warps done reading this W buffer

        if (tid == 0 && ci < NCHUNK - 2){
            int nc = ci + 2;
            uint32_t mb = (nc & 1) ? mb1 : mb0;
            MBAR_EXPECT(mb, CHUNK_B);
            BULK_CP(base + (nc & 1 ? SM_W1 : SM_W0),
                    (const char*)g_wpack + (size_t)nc*CHUNK_B, CHUNK_B, mb);
        }
    }

    // ---- epilogue 2: + bo, store to out [o][l] ----
    float* ob = out + (size_t)b*CSL + (size_t)s*Ll + l0t;
    #pragma unroll
    for (int mt = 0; mt < 3; mt++){
        #pragma unroll
        for (int nt = 0; nt < 4; nt++){
            int o0 = m0 + mt*16 + g;
            int l  = lw0 + nt*8 + t*2;
            #pragma unroll
            for (int h = 0; h < 2; h++){
                int o = o0 + h*8;
                float2 r;
                r.x = d[mt][nt][2*h]     + bo_s[o];
                r.y = d[mt][nt][2*h + 1] + bo_s[o];
                *(float2*)(ob + (size_t)o*SL + l) = r;
            }
        }
    }
}

extern "C" void kernel_launch(void* const* d_in, const int* in_sizes, int n_in,
                              void* d_out, int out_size)
{
    const float* query = (const float*)d_in[0];
    const float* key   = (const float*)d_in[1];
    const float* value = (const float*)d_in[2];
    const float* ipw   = (const float*)d_in[3];
    const float* ipb   = (const float*)d_in[4];
    const float* opw   = (const float*)d_in[5];
    const float* opb   = (const float*)d_in[6];
    float* out = (float*)d_out;

    cudaFuncSetAttribute(k_main, cudaFuncAttributeMaxDynamicSharedMemorySize, DSMEM_BYTES);

    k_q<<<Bx*Ss, 256>>>(query, ipw, ipb, opw);
    k_kbar<<<Bx*Ss, 512>>>(key, ipw, ipb);
    k_main<<<Bx*Ss*(Ll/TL), 256, DSMEM_BYTES>>>(value, ipb, opb, out);
}

// round 12
// speedup vs baseline: 2.4257x; 1.0096x over previous
#include <cuda_runtime.h>
#include <cuda_fp16.h>
#include <cstdint>

// Problem constants: B=4, C=192, S=64, L=512
#define Bx 4
#define Cc 192
#define Ss 64
#define Ll 512
#define SL (Ss*Ll)            // 32768
#define CSL ((size_t)Cc*SL)   // 6291456

#define TL 64                 // l-tile per block

// W packing: per 32-k chunk, [hi image][lo image]; each image 192 rows x 40 halves (32 data + 8 pad)
#define WPITCH 40
#define HIMG_E (Cc*WPITCH)        // 7680 elems
#define CHUNK_E (2*HIMG_E)        // 15360 elems
#define CHUNK_B (CHUNK_E*2)       // 30720 bytes
#define HIMG_B (HIMG_E*2)         // 15360 bytes
// unified: chunks 0..5 = wv (k 0..191), chunks 6..11 = wo
#define NCHUNK 12

__device__ __align__(16) __half g_wpack[NCHUNK*CHUNK_E];
__device__ float g_ctx[Bx*Ss*Cc];      // ctx[(b*64+s)*192 + c]
__device__ float g_sc[Bx*Ss*Ll];       // softmax scores
__device__ float g_kbar[Bx*Ss*Cc];     // weighted key sums

// X smem: [k=192 rows][l=64], pitch 72 halves (64 data + 8 pad), single fp16 image
#define XPITCH 72

// dynamic smem layout (bytes)
#define SM_W0   0
#define SM_W1   CHUNK_B                       // 30720
#define SM_X    (2*CHUNK_B)                   // 61440
#define SM_CTX  (SM_X + Cc*XPITCH*2)          // 89088
#define SM_BV   (SM_CTX + Cc*4)
#define SM_BO   (SM_BV + Cc*4)
#define DSMEM_BYTES (SM_BO + Cc*4)            // 91392

// ---------------- PTX helpers (base sm_103 target only) ----------------
__device__ __forceinline__ uint32_t smem_u32(const void* p){
    return (uint32_t)__cvta_generic_to_shared(p);
}
#define MBAR_INIT(a, n)  asm volatile("mbarrier.init.shared.b64 [%0], %1;" :: "r"(a), "r"(n) : "memory")
#define MBAR_EXPECT(a, n) asm volatile("mbarrier.arrive.expect_tx.shared.b64 _, [%0], %1;" :: "r"(a), "r"(n) : "memory")
// Bounded wait: protocol bug => wrong answer, never a hang.
#define MBAR_WAIT(a, ph) do { \
    uint32_t _m = (a); uint32_t _p = (ph); uint32_t _done = 0; \
    for (int _i = 0; _i < 2000000 && !_done; _i++){ \
        asm volatile("{\n\t.reg .pred p;\n\t" \
            "mbarrier.try_wait.parity.shared.b64 p, [%1], %2;\n\t" \
            "selp.b32 %0, 1, 0, p;\n\t}" : "=r"(_done) : "r"(_m), "r"(_p) : "memory"); \
    } } while(0)
#define BULK_CP(dst, src, bytes, mbar) \
    asm volatile("cp.async.bulk.shared::cta.global.mbarrier::complete_tx::bytes [%0], [%1], %2, [%3];" \
        :: "r"(dst), "l"(src), "r"(bytes), "r"(mbar) : "memory")
#define FENCE_ASYNC() asm volatile("fence.proxy.async.shared::cta;" ::: "memory")

__device__ __forceinline__ void ldsm4(uint32_t r[4], uint32_t a){
    asm volatile("ldmatrix.sync.aligned.m8n8.x4.shared.b16 {%0,%1,%2,%3}, [%4];"
        : "=r"(r[0]), "=r"(r[1]), "=r"(r[2]), "=r"(r[3]) : "r"(a));
}
__device__ __forceinline__ void ldsm4t(uint32_t r[4], uint32_t a){
    asm volatile("ldmatrix.sync.aligned.m8n8.x4.trans.shared.b16 {%0,%1,%2,%3}, [%4];"
        : "=r"(r[0]), "=r"(r[1]), "=r"(r[2]), "=r"(r[3]) : "r"(a));
}
__device__ __forceinline__ void mma16816(float d[4], const uint32_t a[4], uint32_t b0, uint32_t b1){
    asm volatile("mma.sync.aligned.m16n8k16.row.col.f32.f16.f16.f32 "
        "{%0,%1,%2,%3}, {%4,%5,%6,%7}, {%8,%9}, {%0,%1,%2,%3};"
        : "+f"(d[0]), "+f"(d[1]), "+f"(d[2]), "+f"(d[3])
        : "r"(a[0]), "r"(a[1]), "r"(a[2]), "r"(a[3]), "r"(b0), "r"(b1));
}
__device__ __forceinline__ uint32_t pack_h2(float x, float y){
    __half a = __float2half(x), b = __float2half(y);
    return ((uint32_t)__half_as_ushort(b) << 16) | (uint32_t)__half_as_ushort(a);
}

// ---------------- K1a: weight pack (blocks 0..71) + q-dot + softmax -> scores ----------------
// 512 threads, one l per thread: doubled memory parallelism vs R11.
__global__ void __launch_bounds__(512) k_q(
    const float* __restrict__ query, const float* __restrict__ ipw,
    const float* __restrict__ ipb,   const float* __restrict__ opw)
{
    __shared__ float wq_s[Cc];
    __shared__ float red[16];
    __shared__ float bcast;

    int tid = threadIdx.x;
    int bs  = blockIdx.x;
    int b = bs >> 6, s = bs & 63;
    int warp = tid >> 5, lane = tid & 31;

    // ---- merged weight pack: fp16 hi/lo, 32-k chunks [n][k] pitch-40 ----
    if (bs < 72){
        int i = bs*512 + tid;                 // 72*512 = 36864 = Cc*Cc
        int n = i / Cc, k = i % Cc;
        int kc = k >> 5, kk = k & 31;
        {
            float w = ipw[(size_t)(1 + Cc + n)*Cc + k];      // wv[n][k]
            __half hi = __float2half(w);
            __half lo = __float2half(w - __half2float(hi));
            int off = kc*CHUNK_E + n*WPITCH + kk;
            g_wpack[off]          = hi;
            g_wpack[off + HIMG_E] = lo;
        }
        {
            float w = opw[(size_t)n*Cc + k];                  // wo[n][k]
            __half hi = __float2half(w);
            __half lo = __float2half(w - __half2float(hi));
            int off = (6 + kc)*CHUNK_E + n*WPITCH + kk;
            g_wpack[off]          = hi;
            g_wpack[off + HIMG_E] = lo;
        }
    }

    if (tid < Cc) wq_s[tid] = ipw[tid];
    __syncthreads();

    // q for l = tid
    const float* qb = query + (size_t)b*CSL + (size_t)s*Ll + tid;
    float q = ipb[0];
    #pragma unroll 8
    for (int c = 0; c < Cc; c++)
        q = fmaf(wq_s[c], qb[(size_t)c*SL], q);

    // softmax over 512 (16 warps)
    float m = q;
    #pragma unroll
    for (int o = 16; o; o >>= 1) m = fmaxf(m, __shfl_xor_sync(0xffffffffu, m, o));
    if (!lane) red[warp] = m;
    __syncthreads();
    if (tid == 0){ float mm = red[0]; for (int i = 1; i < 16; i++) mm = fmaxf(mm, red[i]); bcast = mm; }
    __syncthreads();
    float M = bcast;
    float e = expf(q - M);
    float sum = e;
    #pragma unroll
    for (int o = 16; o; o >>= 1) sum += __shfl_xor_sync(0xffffffffu, sum, o);
    __syncthreads();   // everyone has read bcast(M)
    if (!lane) red[warp] = sum;
    __syncthreads();
    if (tid == 0){ float ss = 0.f; for (int i = 0; i < 16; i++) ss += red[i]; bcast = 1.f/ss; }
    __syncthreads();
    g_sc[(size_t)bs*Ll + tid] = e * bcast;
}

// ---------------- K1b: kbar[c] = sum_l key[b,c,s,l]*sc[l] ----------------
// grid (256, 2), 512 threads; 16 warps x 6 rows = 96 c-rows per block; float4 loads.
__global__ void __launch_bounds__(512) k_kbar(const float* __restrict__ key)
{
    __shared__ float sc_s[Ll];

    int tid = threadIdx.x;
    int bs = blockIdx.x, cg = blockIdx.y;
    int b = bs >> 6, s = bs & 63;
    int w = tid >> 5, lane = tid & 31;

    sc_s[tid] = g_sc[(size_t)bs*Ll + tid];
    __syncthreads();

    int c0 = cg*96 + w*6;
    const float* kb = key + (size_t)b*CSL + (size_t)s*Ll + (size_t)c0*SL + 4*lane;

    float acc[6];
    #pragma unroll
    for (int r = 0; r < 6; r++) acc[r] = 0.f;

    #pragma unroll
    for (int j = 0; j < 4; j++){
        float4 s4 = *(const float4*)(sc_s + 4*lane + 128*j);
        #pragma unroll
        for (int r = 0; r < 6; r++){
            float4 kv = *(const float4*)(kb + (size_t)r*SL + 128*j);
            acc[r] = fmaf(kv.x, s4.x, fmaf(kv.y, s4.y, fmaf(kv.z, s4.z, fmaf(kv.w, s4.w, acc[r]))));
        }
    }
    #pragma unroll
    for (int r = 0; r < 6; r++){
        float a = acc[r];
        #pragma unroll
        for (int o = 16; o; o >>= 1) a += __shfl_xor_sync(0xffffffffu, a, o);
        if (!lane) g_kbar[(size_t)bs*Cc + c0 + r] = a;
    }
}

// ---------------- K1c: ctx[c] = wk[c,:].kbar + bk[c] ----------------
__global__ void __launch_bounds__(192) k_ctx(
    const float* __restrict__ ipw, const float* __restrict__ ipb)
{
    __shared__ float kb_s[Cc];
    int tid = threadIdx.x;
    int bs = blockIdx.x;
    kb_s[tid] = g_kbar[(size_t)bs*Cc + tid];
    __syncthreads();
    const float* wkr = ipw + (size_t)(1 + tid)*Cc;
    float a = ipb[1 + tid];
    #pragma unroll 8
    for (int j = 0; j < Cc; j++) a = fmaf(wkr[j], kb_s[j], a);
    g_ctx[(size_t)bs*Cc + tid] = a;
}

// ---------------- K2: mma.sync fp16 2-product, double-buffered 32-k W chunks (R9-proven) ----------------
// 256 threads, 8 warps: (wid&3) -> n rows [48*(wid&3), +48) as 3 m16 tiles,
// (wid>>2) -> l cols [32*(wid>>2), +32) as 4 n8 tiles. D[n][l]. A=W (ldsm), B=X (ldsm.trans).
__global__ void __launch_bounds__(256, 2) k_main(
    const float* __restrict__ value,
    const float* __restrict__ ipb, const float* __restrict__ opb,
    float* __restrict__ out)
{
    extern __shared__ char dsm[];
    __shared__ __align__(8) unsigned long long s_mb[2];

    float* ctx_s = (float*)(dsm + SM_CTX);
    float* bv_s  = (float*)(dsm + SM_BV);
    float* bo_s  = (float*)(dsm + SM_BO);

    const uint32_t base = smem_u32(dsm);
    const uint32_t mb0 = smem_u32(&s_mb[0]);
    const uint32_t mb1 = smem_u32(&s_mb[1]);

    int tid = threadIdx.x;
    int lane = tid & 31, wid = tid >> 5;
    int blk = blockIdx.x;
    int lt = blk & 7;
    int bs = blk >> 3;
    int b = bs >> 6, s = bs & 63;
    int l0t = lt * TL;

    // init + prefetch chunks 0,1
    if (tid == 0){
        MBAR_INIT(mb0, 1); MBAR_INIT(mb1, 1);
        FENCE_ASYNC();
        MBAR_EXPECT(mb0, CHUNK_B);
        BULK_CP(base + SM_W0, (const char*)g_wpack, CHUNK_B, mb0);
        MBAR_EXPECT(mb1, CHUNK_B);
        BULK_CP(base + SM_W1, (const char*)g_wpack + CHUNK_B, CHUNK_B, mb1);
    }

    for (int i = tid; i < Cc; i += 256){
        ctx_s[i] = g_ctx[(size_t)bs*Cc + i];
        bv_s[i]  = ipb[1 + Cc + i];
        bo_s[i]  = opb[i];
    }

    // ---- load value tile [192 c][64 l] fp32 -> fp16 X [k][l] pitch 72 ----
    {
        const float* vb = value + (size_t)b*CSL + (size_t)s*Ll + l0t;
        char* x = dsm + SM_X;
        #pragma unroll
        for (int it = 0; it < 12; it++){
            int f = tid + 256*it;            // 3072 float4 total
            int row = f >> 4, col = f & 15;  // col in float4 units
            float4 v = *(const float4*)(vb + (size_t)row*SL + (col << 2));
            uint2 hp;
            hp.x = pack_h2(v.x, v.y);
            hp.y = pack_h2(v.z, v.w);
            *(uint2*)(x + row*(XPITCH*2) + (col << 3)) = hp;
        }
    }
    __syncthreads();

    // warp tiling
    int m0  = (wid & 3) * 48;
    int lw0 = (wid >> 2) * 32;
    int g = lane >> 2, t = lane & 3;
    int lmr = (lane & 7) | (((lane >> 3) & 1) << 3);  // ldmatrix row within 16
    int lmc = (lane >> 4) << 3;                        // 0 or 8

    float d[3][4][4];
    #pragma unroll
    for (int a = 0; a < 3; a++)
        #pragma unroll
        for (int nt = 0; nt < 4; nt++)
            #pragma unroll
            for (int q = 0; q < 4; q++) d[a][nt][q] = 0.f;

    const uint32_t x_b = base + SM_X;

    for (int ci = 0; ci < NCHUNK; ci++){
        if (ci == 6){
            // ---- epilogue 1: t = relu(v+bv)*ctx -> fp16 back into X smem ----
            // (post-chunk-5 __syncthreads => all GEMM1 X reads done)
            #pragma unroll
            for (int mt = 0; mt < 3; mt++){
                #pragma unroll
                for (int nt = 0; nt < 4; nt++){
                    int o0 = m0 + mt*16 + g;
                    int l  = lw0 + nt*8 + t*2;
                    #pragma unroll
                    for (int h = 0; h < 2; h++){
                        int o = o0 + h*8;
                        float v0 = fmaxf(d[mt][nt][2*h]     + bv_s[o], 0.f) * ctx_s[o];
                        float v1 = fmaxf(d[mt][nt][2*h + 1] + bv_s[o], 0.f) * ctx_s[o];
                        *(uint32_t*)(dsm + SM_X + o*(XPITCH*2) + l*2) = pack_h2(v0, v1);
                    }
                }
            }
            #pragma unroll
            for (int a = 0; a < 3; a++)
                #pragma unroll
                for (int nt = 0; nt < 4; nt++)
                    #pragma unroll
                    for (int q = 0; q < 4; q++) d[a][nt][q] = 0.f;
            __syncthreads();
        }

        int buf = ci & 1;
        MBAR_WAIT(buf ? mb1 : mb0, (ci >> 1) & 1);
        uint32_t w_b = base + (buf ? SM_W1 : SM_W0);
        int kc32 = (ci < 6 ? ci : ci - 6) * 32;

        #pragma unroll
        for (int ks = 0; ks < 2; ks++){
            // A fragments (weights), hi and lo images
            uint32_t Ah[3][4], Al[3][4];
            #pragma unroll
            for (int mt = 0; mt < 3; mt++){
                uint32_t arow = (uint32_t)((m0 + mt*16 + lmr)*WPITCH + ks*16 + lmc) * 2u;
                ldsm4(Ah[mt], w_b + arow);
                ldsm4(Al[mt], w_b + HIMG_B + arow);
            }
            int kg = kc32 + ks*16;
            #pragma unroll
            for (int ntp = 0; ntp < 2; ntp++){
                uint32_t boff = (uint32_t)((kg + lmr)*XPITCH + lw0 + ntp*16 + lmc) * 2u;
                uint32_t Bh[4];
                ldsm4t(Bh, x_b + boff);
                #pragma unroll
                for (int mt = 0; mt < 3; mt++){
                    mma16816(d[mt][ntp*2],     Ah[mt], Bh[0], Bh[1]);
                    mma16816(d[mt][ntp*2],     Al[mt], Bh[0], Bh[1]);
                    mma16816(d[mt][ntp*2 + 1], Ah[mt], Bh[2], Bh[3]);
                    mma16816(d[mt][ntp*2 + 1], Al[mt], Bh[2], Bh[3]);
                }
            }
        }
        __syncthreads();   // all warps done reading this W buffer

        if (tid == 0 && ci < NCHUNK - 2){
            int nc = ci + 2;
            uint32_t mb = (nc & 1) ? mb1 : mb0;
            MBAR_EXPECT(mb, CHUNK_B);
            BULK_CP(base + (nc & 1 ? SM_W1 : SM_W0),
                    (const char*)g_wpack + (size_t)nc*CHUNK_B, CHUNK_B, mb);
        }
    }

    // ---- epilogue 2: + bo, store to out [o][l] ----
    float* ob = out + (size_t)b*CSL + (size_t)s*Ll + l0t;
    #pragma unroll
    for (int mt = 0; mt < 3; mt++){
        #pragma unroll
        for (int nt = 0; nt < 4; nt++){
            int o0 = m0 + mt*16 + g;
            int l  = lw0 + nt*8 + t*2;
            #pragma unroll
            for (int h = 0; h < 2; h++){
                int o = o0 + h*8;
                float2 r;
                r.x = d[mt][nt][2*h]     + bo_s[o];
                r.y = d[mt][nt][2*h + 1] + bo_s[o];
                *(float2*)(ob + (size_t)o*SL + l) = r;
            }
        }
    }
}

extern "C" void kernel_launch(void* const* d_in, const int* in_sizes, int n_in,
                              void* d_out, int out_size)
{
    const float* query = (const float*)d_in[0];
    const float* key   = (const float*)d_in[1];
    const float* value = (const float*)d_in[2];
    const float* ipw   = (const float*)d_in[3];
    const float* ipb   = (const float*)d_in[4];
    const float* opw   = (const float*)d_in[5];
    const float* opb   = (const float*)d_in[6];
    float* out = (float*)d_out;

    cudaFuncSetAttribute(k_main, cudaFuncAttributeMaxDynamicSharedMemorySize, DSMEM_BYTES);

    k_q<<<Bx*Ss, 512>>>(query, ipw, ipb, opw);
    dim3 kb_grid(Bx*Ss, 2);
    k_kbar<<<kb_grid, 512>>>(key);
    k_ctx<<<Bx*Ss, 192>>>(ipw, ipb);
    k_main<<<Bx*Ss*(Ll/TL), 256, DSMEM_BYTES>>>(value, ipb, opb, out);
}

// round 13
// speedup vs baseline: 2.4814x; 1.0230x over previous
#include <cuda_runtime.h>
#include <cuda_fp16.h>
#include <cstdint>

// Problem constants: B=4, C=192, S=64, L=512
#define Bx 4
#define Cc 192
#define Ss 64
#define Ll 512
#define SL (Ss*Ll)            // 32768
#define CSL ((size_t)Cc*SL)   // 6291456

#define TL 64                 // l-tile per block

// W packing: per 32-k chunk, [hi image][lo image]; each image 192 rows x 40 halves (32 data + 8 pad)
#define WPITCH 40
#define HIMG_E (Cc*WPITCH)        // 7680 elems
#define CHUNK_E (2*HIMG_E)        // 15360 elems
#define CHUNK_B (CHUNK_E*2)       // 30720 bytes
#define HIMG_B (HIMG_E*2)         // 15360 bytes
// unified: chunks 0..5 = wv (k 0..191), chunks 6..11 = wo
#define NCHUNK 12

__device__ __align__(16) __half g_wpack[NCHUNK*CHUNK_E];
__device__ float g_ctx[Bx*Ss*Cc];      // ctx[(b*64+s)*192 + c]
__device__ float g_sc[Bx*Ss*Ll];       // softmax scores
__device__ float g_kbar[Bx*Ss*Cc];     // weighted key sums

// X smem: [k=192 rows][l=64], pitch 72 halves (64 data + 8 pad), single fp16 image
#define XPITCH 72

// dynamic smem layout (bytes)
#define SM_W0   0
#define SM_W1   CHUNK_B                       // 30720
#define SM_X    (2*CHUNK_B)                   // 61440
#define SM_CTX  (SM_X + Cc*XPITCH*2)          // 89088
#define SM_BV   (SM_CTX + Cc*4)
#define SM_BO   (SM_BV + Cc*4)
#define DSMEM_BYTES (SM_BO + Cc*4)            // 91392

// ---------------- PTX helpers (base sm_103 target only) ----------------
__device__ __forceinline__ uint32_t smem_u32(const void* p){
    return (uint32_t)__cvta_generic_to_shared(p);
}
#define MBAR_INIT(a, n)  asm volatile("mbarrier.init.shared.b64 [%0], %1;" :: "r"(a), "r"(n) : "memory")
#define MBAR_EXPECT(a, n) asm volatile("mbarrier.arrive.expect_tx.shared.b64 _, [%0], %1;" :: "r"(a), "r"(n) : "memory")
#define MBAR_ARRIVE(a)   asm volatile("mbarrier.arrive.shared.b64 _, [%0];" :: "r"(a) : "memory")
// ACQUIRE wait: orders the TMA smem writes before our subsequent ldmatrix reads.
// Bounded: protocol bug => wrong answer, never a hang.
#define MBAR_WAIT_ACQ(a, ph) do { \
    uint32_t _m = (a); uint32_t _p = (ph); uint32_t _done = 0; \
    for (int _i = 0; _i < 2000000 && !_done; _i++){ \
        asm volatile("{\n\t.reg .pred p;\n\t" \
            "mbarrier.try_wait.parity.acquire.cta.shared::cta.b64 p, [%1], %2;\n\t" \
            "selp.b32 %0, 1, 0, p;\n\t}" : "=r"(_done) : "r"(_m), "r"(_p) : "memory"); \
    } } while(0)
#define BULK_CP(dst, src, bytes, mbar) \
    asm volatile("cp.async.bulk.shared::cta.global.mbarrier::complete_tx::bytes [%0], [%1], %2, [%3];" \
        :: "r"(dst), "l"(src), "r"(bytes), "r"(mbar) : "memory")
#define FENCE_ASYNC() asm volatile("fence.proxy.async.shared::cta;" ::: "memory")

__device__ __forceinline__ void ldsm4(uint32_t r[4], uint32_t a){
    asm volatile("ldmatrix.sync.aligned.m8n8.x4.shared.b16 {%0,%1,%2,%3}, [%4];"
        : "=r"(r[0]), "=r"(r[1]), "=r"(r[2]), "=r"(r[3]) : "r"(a));
}
__device__ __forceinline__ void ldsm4t(uint32_t r[4], uint32_t a){
    asm volatile("ldmatrix.sync.aligned.m8n8.x4.trans.shared.b16 {%0,%1,%2,%3}, [%4];"
        : "=r"(r[0]), "=r"(r[1]), "=r"(r[2]), "=r"(r[3]) : "r"(a));
}
__device__ __forceinline__ void mma16816(float d[4], const uint32_t a[4], uint32_t b0, uint32_t b1){
    asm volatile("mma.sync.aligned.m16n8k16.row.col.f32.f16.f16.f32 "
        "{%0,%1,%2,%3}, {%4,%5,%6,%7}, {%8,%9}, {%0,%1,%2,%3};"
        : "+f"(d[0]), "+f"(d[1]), "+f"(d[2]), "+f"(d[3])
        : "r"(a[0]), "r"(a[1]), "r"(a[2]), "r"(a[3]), "r"(b0), "r"(b1));
}
__device__ __forceinline__ uint32_t pack_h2(float x, float y){
    __half a = __float2half(x), b = __float2half(y);
    return ((uint32_t)__half_as_ushort(b) << 16) | (uint32_t)__half_as_ushort(a);
}

// ---------------- K1a: weight pack (blocks 0..71) + q-dot + softmax -> scores ----------------
__global__ void __launch_bounds__(512) k_q(
    const float* __restrict__ query, const float* __restrict__ ipw,
    const float* __restrict__ ipb,   const float* __restrict__ opw)
{
    __shared__ float wq_s[Cc];
    __shared__ float red[16];
    __shared__ float bcast;

    int tid = threadIdx.x;
    int bs  = blockIdx.x;
    int b = bs >> 6, s = bs & 63;
    int warp = tid >> 5, lane = tid & 31;

    // ---- merged weight pack: fp16 hi/lo, 32-k chunks [n][k] pitch-40 ----
    if (bs < 72){
        int i = bs*512 + tid;                 // 72*512 = 36864 = Cc*Cc
        int n = i / Cc, k = i % Cc;
        int kc = k >> 5, kk = k & 31;
        {
            float w = ipw[(size_t)(1 + Cc + n)*Cc + k];      // wv[n][k]
            __half hi = __float2half(w);
            __half lo = __float2half(w - __half2float(hi));
            int off = kc*CHUNK_E + n*WPITCH + kk;
            g_wpack[off]          = hi;
            g_wpack[off + HIMG_E] = lo;
        }
        {
            float w = opw[(size_t)n*Cc + k];                  // wo[n][k]
            __half hi = __float2half(w);
            __half lo = __float2half(w - __half2float(hi));
            int off = (6 + kc)*CHUNK_E + n*WPITCH + kk;
            g_wpack[off]          = hi;
            g_wpack[off + HIMG_E] = lo;
        }
    }

    if (tid < Cc) wq_s[tid] = ipw[tid];
    __syncthreads();

    // q for l = tid
    const float* qb = query + (size_t)b*CSL + (size_t)s*Ll + tid;
    float q = ipb[0];
    #pragma unroll 8
    for (int c = 0; c < Cc; c++)
        q = fmaf(wq_s[c], qb[(size_t)c*SL], q);

    // softmax over 512 (16 warps)
    float m = q;
    #pragma unroll
    for (int o = 16; o; o >>= 1) m = fmaxf(m, __shfl_xor_sync(0xffffffffu, m, o));
    if (!lane) red[warp] = m;
    __syncthreads();
    if (tid == 0){ float mm = red[0]; for (int i = 1; i < 16; i++) mm = fmaxf(mm, red[i]); bcast = mm; }
    __syncthreads();
    float M = bcast;
    float e = expf(q - M);
    float sum = e;
    #pragma unroll
    for (int o = 16; o; o >>= 1) sum += __shfl_xor_sync(0xffffffffu, sum, o);
    __syncthreads();
    if (!lane) red[warp] = sum;
    __syncthreads();
    if (tid == 0){ float ss = 0.f; for (int i = 0; i < 16; i++) ss += red[i]; bcast = 1.f/ss; }
    __syncthreads();
    g_sc[(size_t)bs*Ll + tid] = e * bcast;
}

// ---------------- K1b: kbar[c] = sum_l key[b,c,s,l]*sc[l] ----------------
__global__ void __launch_bounds__(512) k_kbar(const float* __restrict__ key)
{
    __shared__ float sc_s[Ll];

    int tid = threadIdx.x;
    int bs = blockIdx.x, cg = blockIdx.y;
    int b = bs >> 6, s = bs & 63;
    int w = tid >> 5, lane = tid & 31;

    sc_s[tid] = g_sc[(size_t)bs*Ll + tid];
    __syncthreads();

    int c0 = cg*96 + w*6;
    const float* kb = key + (size_t)b*CSL + (size_t)s*Ll + (size_t)c0*SL + 4*lane;

    float acc[6];
    #pragma unroll
    for (int r = 0; r < 6; r++) acc[r] = 0.f;

    #pragma unroll
    for (int j = 0; j < 4; j++){
        float4 s4 = *(const float4*)(sc_s + 4*lane + 128*j);
        #pragma unroll
        for (int r = 0; r < 6; r++){
            float4 kv = *(const float4*)(kb + (size_t)r*SL + 128*j);
            acc[r] = fmaf(kv.x, s4.x, fmaf(kv.y, s4.y, fmaf(kv.z, s4.z, fmaf(kv.w, s4.w, acc[r]))));
        }
    }
    #pragma unroll
    for (int r = 0; r < 6; r++){
        float a = acc[r];
        #pragma unroll
        for (int o = 16; o; o >>= 1) a += __shfl_xor_sync(0xffffffffu, a, o);
        if (!lane) g_kbar[(size_t)bs*Cc + c0 + r] = a;
    }
}

// ---------------- K1c: ctx[c] = wk[c,:].kbar + bk[c] ----------------
__global__ void __launch_bounds__(192) k_ctx(
    const float* __restrict__ ipw, const float* __restrict__ ipb)
{
    __shared__ float kb_s[Cc];
    int tid = threadIdx.x;
    int bs = blockIdx.x;
    kb_s[tid] = g_kbar[(size_t)bs*Cc + tid];
    __syncthreads();
    const float* wkr = ipw + (size_t)(1 + tid)*Cc;
    float a = ipb[1 + tid];
    #pragma unroll 8
    for (int j = 0; j < Cc; j++) a = fmaf(wkr[j], kb_s[j], a);
    g_ctx[(size_t)bs*Cc + tid] = a;
}

// ---------------- K2: mma.sync fp16 2-product, ASYNC empty/full W pipeline ----------------
// 256 threads, 8 warps: (wid&3) -> n rows [48*(wid&3), +48) as 3 m16 tiles,
// (wid>>2) -> l cols [32*(wid>>2), +32) as 4 n8 tiles. D[n][l].
// Consumers: acquire-wait full[buf]; after last ldsm of chunk: __syncwarp + release-arrive empty[buf].
// Producer (tid 0): acquire-wait empty[buf], fence.proxy.async, expect_tx + bulk copy.
__global__ void __launch_bounds__(256, 2) k_main(
    const float* __restrict__ value,
    const float* __restrict__ ipb, const float* __restrict__ opb,
    float* __restrict__ out)
{
    extern __shared__ char dsm[];
    __shared__ __align__(8) unsigned long long s_mb[4];  // full0, full1, empty0, empty1

    float* ctx_s = (float*)(dsm + SM_CTX);
    float* bv_s  = (float*)(dsm + SM_BV);
    float* bo_s  = (float*)(dsm + SM_BO);

    const uint32_t base = smem_u32(dsm);
    const uint32_t full0  = smem_u32(&s_mb[0]);
    const uint32_t full1  = smem_u32(&s_mb[1]);
    const uint32_t empty0 = smem_u32(&s_mb[2]);
    const uint32_t empty1 = smem_u32(&s_mb[3]);

    int tid = threadIdx.x;
    int lane = tid & 31, wid = tid >> 5;
    int blk = blockIdx.x;
    int lt = blk & 7;
    int bs = blk >> 3;
    int b = bs >> 6, s = bs & 63;
    int l0t = lt * TL;

    // init + prefetch chunks 0,1
    if (tid == 0){
        MBAR_INIT(full0, 1); MBAR_INIT(full1, 1);
        MBAR_INIT(empty0, 8); MBAR_INIT(empty1, 8);
        FENCE_ASYNC();
        MBAR_EXPECT(full0, CHUNK_B);
        BULK_CP(base + SM_W0, (const char*)g_wpack, CHUNK_B, full0);
        MBAR_EXPECT(full1, CHUNK_B);
        BULK_CP(base + SM_W1, (const char*)g_wpack + CHUNK_B, CHUNK_B, full1);
    }

    for (int i = tid; i < Cc; i += 256){
        ctx_s[i] = g_ctx[(size_t)bs*Cc + i];
        bv_s[i]  = ipb[1 + Cc + i];
        bo_s[i]  = opb[i];
    }

    // ---- load value tile [192 c][64 l] fp32 -> fp16 X [k][l] pitch 72 ----
    {
        const float* vb = value + (size_t)b*CSL + (size_t)s*Ll + l0t;
        char* x = dsm + SM_X;
        #pragma unroll
        for (int it = 0; it < 12; it++){
            int f = tid + 256*it;            // 3072 float4 total
            int row = f >> 4, col = f & 15;  // col in float4 units
            float4 v = *(const float4*)(vb + (size_t)row*SL + (col << 2));
            uint2 hp;
            hp.x = pack_h2(v.x, v.y);
            hp.y = pack_h2(v.z, v.w);
            *(uint2*)(x + row*(XPITCH*2) + (col << 3)) = hp;
        }
    }
    __syncthreads();   // X visible; mbarrier inits visible to all warps

    // warp tiling
    int m0  = (wid & 3) * 48;
    int lw0 = (wid >> 2) * 32;
    int g = lane >> 2, t = lane & 3;
    int lmr = (lane & 7) | (((lane >> 3) & 1) << 3);  // ldmatrix row within 16
    int lmc = (lane >> 4) << 3;                        // 0 or 8

    float d[3][4][4];
    #pragma unroll
    for (int a = 0; a < 3; a++)
        #pragma unroll
        for (int nt = 0; nt < 4; nt++)
            #pragma unroll
            for (int q = 0; q < 4; q++) d[a][nt][q] = 0.f;

    const uint32_t x_b = base + SM_X;

    for (int ci = 0; ci < NCHUNK; ci++){
        if (ci == 6){
            // ---- epilogue 1: t = relu(v+bv)*ctx -> fp16 back into X smem ----
            __syncthreads();   // all warps finished GEMM1 X reads
            #pragma unroll
            for (int mt = 0; mt < 3; mt++){
                #pragma unroll
                for (int nt = 0; nt < 4; nt++){
                    int o0 = m0 + mt*16 + g;
                    int l  = lw0 + nt*8 + t*2;
                    #pragma unroll
                    for (int h = 0; h < 2; h++){
                        int o = o0 + h*8;
                        float v0 = fmaxf(d[mt][nt][2*h]     + bv_s[o], 0.f) * ctx_s[o];
                        float v1 = fmaxf(d[mt][nt][2*h + 1] + bv_s[o], 0.f) * ctx_s[o];
                        *(uint32_t*)(dsm + SM_X + o*(XPITCH*2) + l*2) = pack_h2(v0, v1);
                    }
                }
            }
            #pragma unroll
            for (int a = 0; a < 3; a++)
                #pragma unroll
                for (int nt = 0; nt < 4; nt++)
                    #pragma unroll
                    for (int q = 0; q < 4; q++) d[a][nt][q] = 0.f;
            __syncthreads();   // new X visible before GEMM2 reads
        }

        int buf = ci & 1;
        uint32_t fullb  = buf ? full1  : full0;
        uint32_t emptyb = buf ? empty1 : empty0;
        MBAR_WAIT_ACQ(fullb, (ci >> 1) & 1);
        uint32_t w_b = base + (buf ? SM_W1 : SM_W0);
        int kc32 = (ci < 6 ? ci : ci - 6) * 32;

        #pragma unroll
        for (int ks = 0; ks < 2; ks++){
            // A fragments (weights), hi and lo images
            uint32_t Ah[3][4], Al[3][4];
            #pragma unroll
            for (int mt = 0; mt < 3; mt++){
                uint32_t arow = (uint32_t)((m0 + mt*16 + lmr)*WPITCH + ks*16 + lmc) * 2u;
                ldsm4(Ah[mt], w_b + arow);
                ldsm4(Al[mt], w_b + HIMG_B + arow);
            }
            int kg = kc32 + ks*16;
            #pragma unroll
            for (int ntp = 0; ntp < 2; ntp++){
                uint32_t boff = (uint32_t)((kg + lmr)*XPITCH + lw0 + ntp*16 + lmc) * 2u;
                uint32_t Bh[4];
                ldsm4t(Bh, x_b + boff);
                #pragma unroll
                for (int mt = 0; mt < 3; mt++){
                    mma16816(d[mt][ntp*2],     Ah[mt], Bh[0], Bh[1]);
                    mma16816(d[mt][ntp*2],     Al[mt], Bh[0], Bh[1]);
                    mma16816(d[mt][ntp*2 + 1], Ah[mt], Bh[2], Bh[3]);
                    mma16816(d[mt][ntp*2 + 1], Al[mt], Bh[2], Bh[3]);
                }
            }
        }

        // this warp is done reading chunk ci's W buffer
        __syncwarp();
        if (lane == 0) MBAR_ARRIVE(emptyb);   // release: orders our ldsm reads before the arrive

        // producer: once all 8 warps drained this buffer, refill with chunk ci+2
        if (tid == 0 && ci < NCHUNK - 2){
            int nc = ci + 2;
            MBAR_WAIT_ACQ(emptyb, (ci >> 1) & 1);
            FENCE_ASYNC();                     // generic reads -> async-proxy write ordering
            MBAR_EXPECT(fullb, CHUNK_B);
            BULK_CP(base + (buf ? SM_W1 : SM_W0),
                    (const char*)g_wpack + (size_t)nc*CHUNK_B, CHUNK_B, fullb);
        }
    }

    // ---- epilogue 2: + bo, store to out [o][l] ----
    float* ob = out + (size_t)b*CSL + (size_t)s*Ll + l0t;
    #pragma unroll
    for (int mt = 0; mt < 3; mt++){
        #pragma unroll
        for (int nt = 0; nt < 4; nt++){
            int o0 = m0 + mt*16 + g;
            int l  = lw0 + nt*8 + t*2;
            #pragma unroll
            for (int h = 0; h < 2; h++){
                int o = o0 + h*8;
                float2 r;
                r.x = d[mt][nt][2*h]     + bo_s[o];
                r.y = d[mt][nt][2*h + 1] + bo_s[o];
                *(float2*)(ob + (size_t)o*SL + l) = r;
            }
        }
    }
}

extern "C" void kernel_launch(void* const* d_in, const int* in_sizes, int n_in,
                              void* d_out, int out_size)
{
    const float* query = (const float*)d_in[0];
    const float* key   = (const float*)d_in[1];
    const float* value = (const float*)d_in[2];
    const float* ipw   = (const float*)d_in[3];
    const float* ipb   = (const float*)d_in[4];
    const float* opw   = (const float*)d_in[5];
    const float* opb   = (const float*)d_in[6];
    float* out = (float*)d_out;

    cudaFuncSetAttribute(k_main, cudaFuncAttributeMaxDynamicSharedMemorySize, DSMEM_BYTES);

    k_q<<<Bx*Ss, 512>>>(query, ipw, ipb, opw);
    dim3 kb_grid(Bx*Ss, 2);
    k_kbar<<<kb_grid, 512>>>(key);
    k_ctx<<<Bx*Ss, 192>>>(ipw, ipb);
    k_main<<<Bx*Ss*(Ll/TL), 256, DSMEM_BYTES>>>(value, ipb, opb, out);
}

// round 14
// speedup vs baseline: 2.8931x; 1.1659x over previous
#include <cuda_runtime.h>
#include <cuda_fp16.h>
#include <cstdint>

// Problem constants: B=4, C=192, S=64, L=512
#define Bx 4
#define Cc 192
#define Ss 64
#define Ll 512
#define SL (Ss*Ll)            // 32768
#define CSL ((size_t)Cc*SL)   // 6291456

#define TL 64                 // l-tile per block

// W packing: per 32-k chunk, SINGLE fp16 image; 192 rows x 40 halves (32 data + 8 pad)
#define WPITCH 40
#define CHUNK_E (Cc*WPITCH)       // 7680 elems
#define CHUNK_B (CHUNK_E*2)       // 15360 bytes
// unified: chunks 0..5 = wv (k 0..191), chunks 6..11 = wo
#define NCHUNK 12

__device__ __align__(16) __half g_wpack[NCHUNK*CHUNK_E];
__device__ float g_ctx[Bx*Ss*Cc];      // ctx[(b*64+s)*192 + c]
__device__ float g_sc[Bx*Ss*Ll];       // softmax scores
__device__ float g_kbar[Bx*Ss*Cc];     // weighted key sums

// X smem: [k=192 rows][l=64], pitch 72 halves (64 data + 8 pad), single fp16 image
#define XPITCH 72

// dynamic smem layout (bytes)
#define SM_W0   0
#define SM_W1   CHUNK_B                       // 15360
#define SM_X    (2*CHUNK_B)                   // 30720
#define SM_CTX  (SM_X + Cc*XPITCH*2)          // 58368
#define SM_BV   (SM_CTX + Cc*4)
#define SM_BO   (SM_BV + Cc*4)
#define DSMEM_BYTES (SM_BO + Cc*4)            // 60672

// ---------------- PTX helpers (base sm_103 target only) ----------------
__device__ __forceinline__ uint32_t smem_u32(const void* p){
    return (uint32_t)__cvta_generic_to_shared(p);
}
#define MBAR_INIT(a, n)  asm volatile("mbarrier.init.shared.b64 [%0], %1;" :: "r"(a), "r"(n) : "memory")
#define MBAR_EXPECT(a, n) asm volatile("mbarrier.arrive.expect_tx.shared.b64 _, [%0], %1;" :: "r"(a), "r"(n) : "memory")
#define MBAR_ARRIVE(a)   asm volatile("mbarrier.arrive.shared.b64 _, [%0];" :: "r"(a) : "memory")
// ACQUIRE wait: orders the TMA smem writes before our subsequent ldmatrix reads.
// Bounded: protocol bug => wrong answer, never a hang.
#define MBAR_WAIT_ACQ(a, ph) do { \
    uint32_t _m = (a); uint32_t _p = (ph); uint32_t _done = 0; \
    for (int _i = 0; _i < 2000000 && !_done; _i++){ \
        asm volatile("{\n\t.reg .pred p;\n\t" \
            "mbarrier.try_wait.parity.acquire.cta.shared::cta.b64 p, [%1], %2;\n\t" \
            "selp.b32 %0, 1, 0, p;\n\t}" : "=r"(_done) : "r"(_m), "r"(_p) : "memory"); \
    } } while(0)
#define BULK_CP(dst, src, bytes, mbar) \
    asm volatile("cp.async.bulk.shared::cta.global.mbarrier::complete_tx::bytes [%0], [%1], %2, [%3];" \
        :: "r"(dst), "l"(src), "r"(bytes), "r"(mbar) : "memory")
#define FENCE_ASYNC() asm volatile("fence.proxy.async.shared::cta;" ::: "memory")

__device__ __forceinline__ void ldsm4(uint32_t r[4], uint32_t a){
    asm volatile("ldmatrix.sync.aligned.m8n8.x4.shared.b16 {%0,%1,%2,%3}, [%4];"
        : "=r"(r[0]), "=r"(r[1]), "=r"(r[2]), "=r"(r[3]) : "r"(a));
}
__device__ __forceinline__ void ldsm4t(uint32_t r[4], uint32_t a){
    asm volatile("ldmatrix.sync.aligned.m8n8.x4.trans.shared.b16 {%0,%1,%2,%3}, [%4];"
        : "=r"(r[0]), "=r"(r[1]), "=r"(r[2]), "=r"(r[3]) : "r"(a));
}
__device__ __forceinline__ void mma16816(float d[4], const uint32_t a[4], uint32_t b0, uint32_t b1){
    asm volatile("mma.sync.aligned.m16n8k16.row.col.f32.f16.f16.f32 "
        "{%0,%1,%2,%3}, {%4,%5,%6,%7}, {%8,%9}, {%0,%1,%2,%3};"
        : "+f"(d[0]), "+f"(d[1]), "+f"(d[2]), "+f"(d[3])
        : "r"(a[0]), "r"(a[1]), "r"(a[2]), "r"(a[3]), "r"(b0), "r"(b1));
}
__device__ __forceinline__ uint32_t pack_h2(float x, float y){
    __half a = __float2half(x), b = __float2half(y);
    return ((uint32_t)__half_as_ushort(b) << 16) | (uint32_t)__half_as_ushort(a);
}

// ---------------- K1a: weight pack (blocks 0..71) + q-dot + softmax -> scores ----------------
__global__ void __launch_bounds__(512) k_q(
    const float* __restrict__ query, const float* __restrict__ ipw,
    const float* __restrict__ ipb,   const float* __restrict__ opw)
{
    __shared__ float wq_s[Cc];
    __shared__ float red[16];
    __shared__ float bcast;

    int tid = threadIdx.x;
    int bs  = blockIdx.x;
    int b = bs >> 6, s = bs & 63;
    int warp = tid >> 5, lane = tid & 31;

    // ---- merged weight pack: fp16 (single image), 32-k chunks [n][k] pitch-40 ----
    if (bs < 72){
        int i = bs*512 + tid;                 // 72*512 = 36864 = Cc*Cc
        int n = i / Cc, k = i % Cc;
        int kc = k >> 5, kk = k & 31;
        g_wpack[kc*CHUNK_E + n*WPITCH + kk] =
            __float2half(ipw[(size_t)(1 + Cc + n)*Cc + k]);          // wv[n][k]
        g_wpack[(6 + kc)*CHUNK_E + n*WPITCH + kk] =
            __float2half(opw[(size_t)n*Cc + k]);                      // wo[n][k]
    }

    if (tid < Cc) wq_s[tid] = ipw[tid];
    __syncthreads();

    // q for l = tid
    const float* qb = query + (size_t)b*CSL + (size_t)s*Ll + tid;
    float q = ipb[0];
    #pragma unroll 8
    for (int c = 0; c < Cc; c++)
        q = fmaf(wq_s[c], qb[(size_t)c*SL], q);

    // softmax over 512 (16 warps)
    float m = q;
    #pragma unroll
    for (int o = 16; o; o >>= 1) m = fmaxf(m, __shfl_xor_sync(0xffffffffu, m, o));
    if (!lane) red[warp] = m;
    __syncthreads();
    if (tid == 0){ float mm = red[0]; for (int i = 1; i < 16; i++) mm = fmaxf(mm, red[i]); bcast = mm; }
    __syncthreads();
    float M = bcast;
    float e = expf(q - M);
    float sum = e;
    #pragma unroll
    for (int o = 16; o; o >>= 1) sum += __shfl_xor_sync(0xffffffffu, sum, o);
    __syncthreads();
    if (!lane) red[warp] = sum;
    __syncthreads();
    if (tid == 0){ float ss = 0.f; for (int i = 0; i < 16; i++) ss += red[i]; bcast = 1.f/ss; }
    __syncthreads();
    g_sc[(size_t)bs*Ll + tid] = e * bcast;
}

// ---------------- K1b: kbar[c] = sum_l key[b,c,s,l]*sc[l] ----------------
__global__ void __launch_bounds__(512) k_kbar(const float* __restrict__ key)
{
    __shared__ float sc_s[Ll];

    int tid = threadIdx.x;
    int bs = blockIdx.x, cg = blockIdx.y;
    int b = bs >> 6, s = bs & 63;
    int w = tid >> 5, lane = tid & 31;

    sc_s[tid] = g_sc[(size_t)bs*Ll + tid];
    __syncthreads();

    int c0 = cg*96 + w*6;
    const float* kb = key + (size_t)b*CSL + (size_t)s*Ll + (size_t)c0*SL + 4*lane;

    float acc[6];
    #pragma unroll
    for (int r = 0; r < 6; r++) acc[r] = 0.f;

    #pragma unroll
    for (int j = 0; j < 4; j++){
        float4 s4 = *(const float4*)(sc_s + 4*lane + 128*j);
        #pragma unroll
        for (int r = 0; r < 6; r++){
            float4 kv = *(const float4*)(kb + (size_t)r*SL + 128*j);
            acc[r] = fmaf(kv.x, s4.x, fmaf(kv.y, s4.y, fmaf(kv.z, s4.z, fmaf(kv.w, s4.w, acc[r]))));
        }
    }
    #pragma unroll
    for (int r = 0; r < 6; r++){
        float a = acc[r];
        #pragma unroll
        for (int o = 16; o; o >>= 1) a += __shfl_xor_sync(0xffffffffu, a, o);
        if (!lane) g_kbar[(size_t)bs*Cc + c0 + r] = a;
    }
}

// ---------------- K1c: ctx[c] = wk[c,:].kbar + bk[c] ----------------
__global__ void __launch_bounds__(192) k_ctx(
    const float* __restrict__ ipw, const float* __restrict__ ipb)
{
    __shared__ float kb_s[Cc];
    int tid = threadIdx.x;
    int bs = blockIdx.x;
    kb_s[tid] = g_kbar[(size_t)bs*Cc + tid];
    __syncthreads();
    const float* wkr = ipw + (size_t)(1 + tid)*Cc;
    float a = ipb[1 + tid];
    #pragma unroll 8
    for (int j = 0; j < Cc; j++) a = fmaf(wkr[j], kb_s[j], a);
    g_ctx[(size_t)bs*Cc + tid] = a;
}

// ---------------- K2: mma.sync fp16 SINGLE-product, ASYNC empty/full W pipeline ----------------
// 256 threads, 8 warps: (wid&3) -> n rows [48*(wid&3), +48) as 3 m16 tiles,
// (wid>>2) -> l cols [32*(wid>>2), +32) as 4 n8 tiles. D[n][l].
// Consumers: acquire-wait full[buf]; after last ldsm of chunk: __syncwarp + release-arrive empty[buf].
// Producer (tid 0): acquire-wait empty[buf], fence.proxy.async, expect_tx + bulk copy.
__global__ void __launch_bounds__(256, 3) k_main(
    const float* __restrict__ value,
    const float* __restrict__ ipb, const float* __restrict__ opb,
    float* __restrict__ out)
{
    extern __shared__ char dsm[];
    __shared__ __align__(8) unsigned long long s_mb[4];  // full0, full1, empty0, empty1

    float* ctx_s = (float*)(dsm + SM_CTX);
    float* bv_s  = (float*)(dsm + SM_BV);
    float* bo_s  = (float*)(dsm + SM_BO);

    const uint32_t base = smem_u32(dsm);
    const uint32_t full0  = smem_u32(&s_mb[0]);
    const uint32_t full1  = smem_u32(&s_mb[1]);
    const uint32_t empty0 = smem_u32(&s_mb[2]);
    const uint32_t empty1 = smem_u32(&s_mb[3]);

    int tid = threadIdx.x;
    int lane = tid & 31, wid = tid >> 5;
    int blk = blockIdx.x;
    int lt = blk & 7;
    int bs = blk >> 3;
    int b = bs >> 6, s = bs & 63;
    int l0t = lt * TL;

    // init + prefetch chunks 0,1
    if (tid == 0){
        MBAR_INIT(full0, 1); MBAR_INIT(full1, 1);
        MBAR_INIT(empty0, 8); MBAR_INIT(empty1, 8);
        FENCE_ASYNC();
        MBAR_EXPECT(full0, CHUNK_B);
        BULK_CP(base + SM_W0, (const char*)g_wpack, CHUNK_B, full0);
        MBAR_EXPECT(full1, CHUNK_B);
        BULK_CP(base + SM_W1, (const char*)g_wpack + CHUNK_B, CHUNK_B, full1);
    }

    for (int i = tid; i < Cc; i += 256){
        ctx_s[i] = g_ctx[(size_t)bs*Cc + i];
        bv_s[i]  = ipb[1 + Cc + i];
        bo_s[i]  = opb[i];
    }

    // ---- load value tile [192 c][64 l] fp32 -> fp16 X [k][l] pitch 72 ----
    {
        const float* vb = value + (size_t)b*CSL + (size_t)s*Ll + l0t;
        char* x = dsm + SM_X;
        #pragma unroll
        for (int it = 0; it < 12; it++){
            int f = tid + 256*it;            // 3072 float4 total
            int row = f >> 4, col = f & 15;  // col in float4 units
            float4 v = *(const float4*)(vb + (size_t)row*SL + (col << 2));
            uint2 hp;
            hp.x = pack_h2(v.x, v.y);
            hp.y = pack_h2(v.z, v.w);
            *(uint2*)(x + row*(XPITCH*2) + (col << 3)) = hp;
        }
    }
    __syncthreads();   // X visible; mbarrier inits visible to all warps

    // warp tiling
    int m0  = (wid & 3) * 48;
    int lw0 = (wid >> 2) * 32;
    int g = lane >> 2, t = lane & 3;
    int lmr = (lane & 7) | (((lane >> 3) & 1) << 3);  // ldmatrix row within 16
    int lmc = (lane >> 4) << 3;                        // 0 or 8

    float d[3][4][4];
    #pragma unroll
    for (int a = 0; a < 3; a++)
        #pragma unroll
        for (int nt = 0; nt < 4; nt++)
            #pragma unroll
            for (int q = 0; q < 4; q++) d[a][nt][q] = 0.f;

    const uint32_t x_b = base + SM_X;

    for (int ci = 0; ci < NCHUNK; ci++){
        if (ci == 6){
            // ---- epilogue 1: t = relu(v+bv)*ctx -> fp16 back into X smem ----
            __syncthreads();   // all warps finished GEMM1 X reads
            #pragma unroll
            for (int mt = 0; mt < 3; mt++){
                #pragma unroll
                for (int nt = 0; nt < 4; nt++){
                    int o0 = m0 + mt*16 + g;
                    int l  = lw0 + nt*8 + t*2;
                    #pragma unroll
                    for (int h = 0; h < 2; h++){
                        int o = o0 + h*8;
                        float v0 = fmaxf(d[mt][nt][2*h]     + bv_s[o], 0.f) * ctx_s[o];
                        float v1 = fmaxf(d[mt][nt][2*h + 1] + bv_s[o], 0.f) * ctx_s[o];
                        *(uint32_t*)(dsm + SM_X + o*(XPITCH*2) + l*2) = pack_h2(v0, v1);
                    }
                }
            }
            #pragma unroll
            for (int a = 0; a < 3; a++)
                #pragma unroll
                for (int nt = 0; nt < 4; nt++)
                    #pragma unroll
                    for (int q = 0; q < 4; q++) d[a][nt][q] = 0.f;
            __syncthreads();   // new X visible before GEMM2 reads
        }

        int buf = ci & 1;
        uint32_t fullb  = buf ? full1  : full0;
        uint32_t emptyb = buf ? empty1 : empty0;
        MBAR_WAIT_ACQ(fullb, (ci >> 1) & 1);
        uint32_t w_b = base + (buf ? SM_W1 : SM_W0);
        int kc32 = (ci < 6 ? ci : ci - 6) * 32;

        #pragma unroll
        for (int ks = 0; ks < 2; ks++){
            // A fragments (weights), single fp16 image
            uint32_t Ah[3][4];
            #pragma unroll
            for (int mt = 0; mt < 3; mt++){
                uint32_t arow = (uint32_t)((m0 + mt*16 + lmr)*WPITCH + ks*16 + lmc) * 2u;
                ldsm4(Ah[mt], w_b + arow);
            }
            int kg = kc32 + ks*16;
            #pragma unroll
            for (int ntp = 0; ntp < 2; ntp++){
                uint32_t boff = (uint32_t)((kg + lmr)*XPITCH + lw0 + ntp*16 + lmc) * 2u;
                uint32_t Bh[4];
                ldsm4t(Bh, x_b + boff);
                #pragma unroll
                for (int mt = 0; mt < 3; mt++){
                    mma16816(d[mt][ntp*2],     Ah[mt], Bh[0], Bh[1]);
                    mma16816(d[mt][ntp*2 + 1], Ah[mt], Bh[2], Bh[3]);
                }
            }
        }

        // this warp is done reading chunk ci's W buffer
        __syncwarp();
        if (lane == 0) MBAR_ARRIVE(emptyb);   // release: orders our ldsm reads before the arrive

        // producer: once all 8 warps drained this buffer, refill with chunk ci+2
        if (tid == 0 && ci < NCHUNK - 2){
            int nc = ci + 2;
            MBAR_WAIT_ACQ(emptyb, (ci >> 1) & 1);
            FENCE_ASYNC();                     // generic reads -> async-proxy write ordering
            MBAR_EXPECT(fullb, CHUNK_B);
            BULK_CP(base + (buf ? SM_W1 : SM_W0),
                    (const char*)g_wpack + (size_t)nc*CHUNK_B, CHUNK_B, fullb);
        }
    }

    // ---- epilogue 2: + bo, store to out [o][l] ----
    float* ob = out + (size_t)b*CSL + (size_t)s*Ll + l0t;
    #pragma unroll
    for (int mt = 0; mt < 3; mt++){
        #pragma unroll
        for (int nt = 0; nt < 4; nt++){
            int o0 = m0 + mt*16 + g;
            int l  = lw0 + nt*8 + t*2;
            #pragma unroll
            for (int h = 0; h < 2; h++){
                int o = o0 + h*8;
                float2 r;
                r.x = d[mt][nt][2*h]     + bo_s[o];
                r.y = d[mt][nt][2*h + 1] + bo_s[o];
                *(float2*)(ob + (size_t)o*SL + l) = r;
            }
        }
    }
}

extern "C" void kernel_launch(void* const* d_in, const int* in_sizes, int n_in,
                              void* d_out, int out_size)
{
    const float* query = (const float*)d_in[0];
    const float* key   = (const float*)d_in[1];
    const float* value = (const float*)d_in[2];
    const float* ipw   = (const float*)d_in[3];
    const float* ipb   = (const float*)d_in[4];
    const float* opw   = (const float*)d_in[5];
    const float* opb   = (const float*)d_in[6];
    float* out = (float*)d_out;

    cudaFuncSetAttribute(k_main, cudaFuncAttributeMaxDynamicSharedMemorySize, DSMEM_BYTES);

    k_q<<<Bx*Ss, 512>>>(query, ipw, ipb, opw);
    dim3 kb_grid(Bx*Ss, 2);
    k_kbar<<<kb_grid, 512>>>(key);
    k_ctx<<<Bx*Ss, 192>>>(ipw, ipb);
    k_main<<<Bx*Ss*(Ll/TL), 256, DSMEM_BYTES>>>(value, ipb, opb, out);
}

// round 15
// speedup vs baseline: 2.9799x; 1.0300x over previous
#include <cuda_runtime.h>
#include <cuda_fp16.h>
#include <cstdint>

// Problem constants: B=4, C=192, S=64, L=512
#define Bx 4
#define Cc 192
#define Ss 64
#define Ll 512
#define SL (Ss*Ll)            // 32768
#define CSL ((size_t)Cc*SL)   // 6291456

#define TL 64                 // l-tile per block

// W packing: per 32-k chunk, SINGLE fp16 image; 192 rows x 40 halves (32 data + 8 pad)
#define WPITCH 40
#define CHUNK_E (Cc*WPITCH)       // 7680 elems
#define CHUNK_B (CHUNK_E*2)       // 15360 bytes
// unified: chunks 0..5 = wv (k 0..191), chunks 6..11 = wo
#define NCHUNK 12

__device__ __align__(16) __half g_wpack[NCHUNK*CHUNK_E];
__device__ float g_ctx[Bx*Ss*Cc];      // ctx[(b*64+s)*192 + c]

// X smem: [k=192 rows][l=64], pitch 72 halves (64 data + 8 pad), single fp16 image
#define XPITCH 72

// dynamic smem layout (bytes)
#define SM_W0   0
#define SM_W1   CHUNK_B                       // 15360
#define SM_X    (2*CHUNK_B)                   // 30720
#define SM_CTX  (SM_X + Cc*XPITCH*2)          // 58368
#define SM_BV   (SM_CTX + Cc*4)
#define SM_BO   (SM_BV + Cc*4)
#define DSMEM_BYTES (SM_BO + Cc*4)            // 60672

// ---------------- PTX helpers (base sm_103 target only) ----------------
__device__ __forceinline__ uint32_t smem_u32(const void* p){
    return (uint32_t)__cvta_generic_to_shared(p);
}
#define MBAR_INIT(a, n)  asm volatile("mbarrier.init.shared.b64 [%0], %1;" :: "r"(a), "r"(n) : "memory")
#define MBAR_EXPECT(a, n) asm volatile("mbarrier.arrive.expect_tx.shared.b64 _, [%0], %1;" :: "r"(a), "r"(n) : "memory")
#define MBAR_ARRIVE(a)   asm volatile("mbarrier.arrive.shared.b64 _, [%0];" :: "r"(a) : "memory")
// ACQUIRE wait: orders the TMA smem writes before our subsequent ldmatrix reads.
// Bounded: protocol bug => wrong answer, never a hang.
#define MBAR_WAIT_ACQ(a, ph) do { \
    uint32_t _m = (a); uint32_t _p = (ph); uint32_t _done = 0; \
    for (int _i = 0; _i < 2000000 && !_done; _i++){ \
        asm volatile("{\n\t.reg .pred p;\n\t" \
            "mbarrier.try_wait.parity.acquire.cta.shared::cta.b64 p, [%1], %2;\n\t" \
            "selp.b32 %0, 1, 0, p;\n\t}" : "=r"(_done) : "r"(_m), "r"(_p) : "memory"); \
    } } while(0)
#define BULK_CP(dst, src, bytes, mbar) \
    asm volatile("cp.async.bulk.shared::cta.global.mbarrier::complete_tx::bytes [%0], [%1], %2, [%3];" \
        :: "r"(dst), "l"(src), "r"(bytes), "r"(mbar) : "memory")
#define FENCE_ASYNC() asm volatile("fence.proxy.async.shared::cta;" ::: "memory")

__device__ __forceinline__ void ldsm4(uint32_t r[4], uint32_t a){
    asm volatile("ldmatrix.sync.aligned.m8n8.x4.shared.b16 {%0,%1,%2,%3}, [%4];"
        : "=r"(r[0]), "=r"(r[1]), "=r"(r[2]), "=r"(r[3]) : "r"(a));
}
__device__ __forceinline__ void ldsm4t(uint32_t r[4], uint32_t a){
    asm volatile("ldmatrix.sync.aligned.m8n8.x4.trans.shared.b16 {%0,%1,%2,%3}, [%4];"
        : "=r"(r[0]), "=r"(r[1]), "=r"(r[2]), "=r"(r[3]) : "r"(a));
}
__device__ __forceinline__ void mma16816(float d[4], const uint32_t a[4], uint32_t b0, uint32_t b1){
    asm volatile("mma.sync.aligned.m16n8k16.row.col.f32.f16.f16.f32 "
        "{%0,%1,%2,%3}, {%4,%5,%6,%7}, {%8,%9}, {%0,%1,%2,%3};"
        : "+f"(d[0]), "+f"(d[1]), "+f"(d[2]), "+f"(d[3])
        : "r"(a[0]), "r"(a[1]), "r"(a[2]), "r"(a[3]), "r"(b0), "r"(b1));
}
__device__ __forceinline__ uint32_t pack_h2(float x, float y){
    __half a = __float2half(x), b = __float2half(y);
    return ((uint32_t)__half_as_ushort(b) << 16) | (uint32_t)__half_as_ushort(a);
}

// ---------------- K1: FUSED stage1 ----------------
// 256 blocks (one per bs) x 1024 threads (32 warps).
// pack (blocks 0..35) + q-dot (c-split across 2 halves) + softmax + kbar (32w x 6 rows) + ctx.
__global__ void __launch_bounds__(1024) k_stage(
    const float* __restrict__ query, const float* __restrict__ key,
    const float* __restrict__ ipw,   const float* __restrict__ ipb,
    const float* __restrict__ opw)
{
    __shared__ float wq_s[Cc];
    __shared__ float sc_s[Ll];    // half1 partial staging, then final scores
    __shared__ float kb_s[Cc];
    __shared__ float red[16];
    __shared__ float bcast;

    int tid = threadIdx.x;
    int bs  = blockIdx.x;
    int b = bs >> 6, s = bs & 63;
    int warp = tid >> 5, lane = tid & 31;
    int l = tid & 511, half = tid >> 9;

    // ---- merged weight pack: fp16 single image, 32-k chunks [n][k] pitch-40 ----
    if (bs < 36){
        int i = bs*1024 + tid;                // 36*1024 = 36864 = Cc*Cc
        int n = i / Cc, k = i % Cc;
        int kc = k >> 5, kk = k & 31;
        g_wpack[kc*CHUNK_E + n*WPITCH + kk] =
            __float2half(ipw[(size_t)(1 + Cc + n)*Cc + k]);          // wv[n][k]
        g_wpack[(6 + kc)*CHUNK_E + n*WPITCH + kk] =
            __float2half(opw[(size_t)n*Cc + k]);                      // wo[n][k]
    }

    if (tid < Cc) wq_s[tid] = ipw[tid];
    __syncthreads();

    // ---- q-phase: thread (l, half) reduces 96 c's ----
    const float* qb = query + (size_t)b*CSL + (size_t)(half*96)*SL + (size_t)s*Ll + l;
    float part = half ? 0.f : ipb[0];
    const float* wqh = wq_s + half*96;
    #pragma unroll 8
    for (int c = 0; c < 96; c++)
        part = fmaf(wqh[c], qb[(size_t)c*SL], part);

    if (half) sc_s[l] = part;
    __syncthreads();
    float q = 0.f;
    if (!half) q = part + sc_s[l];

    // ---- softmax over 512 (warps 0..15 hold q; all 1024 hit barriers) ----
    float m = half ? -3.4e38f : q;
    #pragma unroll
    for (int o = 16; o; o >>= 1) m = fmaxf(m, __shfl_xor_sync(0xffffffffu, m, o));
    if (!half && !lane) red[warp] = m;
    __syncthreads();
    if (tid == 0){ float mm = red[0]; for (int i = 1; i < 16; i++) mm = fmaxf(mm, red[i]); bcast = mm; }
    __syncthreads();
    float M = bcast;
    float e = half ? 0.f : expf(q - M);
    float sum = e;
    #pragma unroll
    for (int o = 16; o; o >>= 1) sum += __shfl_xor_sync(0xffffffffu, sum, o);
    __syncthreads();
    if (!half && !lane) red[warp] = sum;
    __syncthreads();
    if (tid == 0){ float ss = 0.f; for (int i = 0; i < 16; i++) ss += red[i]; bcast = 1.f/ss; }
    __syncthreads();
    if (!half) sc_s[l] = e * bcast;   // overwrite staging with final scores
    __syncthreads();

    // ---- kbar: 32 warps x 6 rows, float4 streams ----
    {
        int c0 = warp*6;
        const float* kb = key + (size_t)b*CSL + (size_t)s*Ll + (size_t)c0*SL + 4*lane;
        float acc[6];
        #pragma unroll
        for (int r = 0; r < 6; r++) acc[r] = 0.f;
        #pragma unroll
        for (int j = 0; j < 4; j++){
            float4 s4 = *(const float4*)(sc_s + 4*lane + 128*j);
            #pragma unroll
            for (int r = 0; r < 6; r++){
                float4 kv = *(const float4*)(kb + (size_t)r*SL + 128*j);
                acc[r] = fmaf(kv.x, s4.x, fmaf(kv.y, s4.y, fmaf(kv.z, s4.z, fmaf(kv.w, s4.w, acc[r]))));
            }
        }
        #pragma unroll
        for (int r = 0; r < 6; r++){
            float a = acc[r];
            #pragma unroll
            for (int o = 16; o; o >>= 1) a += __shfl_xor_sync(0xffffffffu, a, o);
            if (!lane) kb_s[c0 + r] = a;
        }
    }
    __syncthreads();

    // ---- ctx: threads 0..191 ----
    if (tid < Cc){
        const float* wkr = ipw + (size_t)(1 + tid)*Cc;
        float a = ipb[1 + tid];
        #pragma unroll 8
        for (int j = 0; j < Cc; j++) a = fmaf(wkr[j], kb_s[j], a);
        g_ctx[(size_t)bs*Cc + tid] = a;
    }
}

// ---------------- K2: mma.sync fp16 SINGLE-product, ASYNC empty/full W pipeline (R14-proven) ----------------
// 256 threads, 8 warps: (wid&3) -> n rows [48*(wid&3), +48) as 3 m16 tiles,
// (wid>>2) -> l cols [32*(wid>>2), +32) as 4 n8 tiles. D[n][l].
__global__ void __launch_bounds__(256, 3) k_main(
    const float* __restrict__ value,
    const float* __restrict__ ipb, const float* __restrict__ opb,
    float* __restrict__ out)
{
    extern __shared__ char dsm[];
    __shared__ __align__(8) unsigned long long s_mb[4];  // full0, full1, empty0, empty1

    float* ctx_s = (float*)(dsm + SM_CTX);
    float* bv_s  = (float*)(dsm + SM_BV);
    float* bo_s  = (float*)(dsm + SM_BO);

    const uint32_t base = smem_u32(dsm);
    const uint32_t full0  = smem_u32(&s_mb[0]);
    const uint32_t full1  = smem_u32(&s_mb[1]);
    const uint32_t empty0 = smem_u32(&s_mb[2]);
    const uint32_t empty1 = smem_u32(&s_mb[3]);

    int tid = threadIdx.x;
    int lane = tid & 31, wid = tid >> 5;
    int blk = blockIdx.x;
    int lt = blk & 7;
    int bs = blk >> 3;
    int b = bs >> 6, s = bs & 63;
    int l0t = lt * TL;

    // init + prefetch chunks 0,1
    if (tid == 0){
        MBAR_INIT(full0, 1); MBAR_INIT(full1, 1);
        MBAR_INIT(empty0, 8); MBAR_INIT(empty1, 8);
        FENCE_ASYNC();
        MBAR_EXPECT(full0, CHUNK_B);
        BULK_CP(base + SM_W0, (const char*)g_wpack, CHUNK_B, full0);
        MBAR_EXPECT(full1, CHUNK_B);
        BULK_CP(base + SM_W1, (const char*)g_wpack + CHUNK_B, CHUNK_B, full1);
    }

    for (int i = tid; i < Cc; i += 256){
        ctx_s[i] = g_ctx[(size_t)bs*Cc + i];
        bv_s[i]  = ipb[1 + Cc + i];
        bo_s[i]  = opb[i];
    }

    // ---- load value tile [192 c][64 l] fp32 -> fp16 X [k][l] pitch 72 ----
    {
        const float* vb = value + (size_t)b*CSL + (size_t)s*Ll + l0t;
        char* x = dsm + SM_X;
        #pragma unroll
        for (int it = 0; it < 12; it++){
            int f = tid + 256*it;            // 3072 float4 total
            int row = f >> 4, col = f & 15;  // col in float4 units
            float4 v = *(const float4*)(vb + (size_t)row*SL + (col << 2));
            uint2 hp;
            hp.x = pack_h2(v.x, v.y);
            hp.y = pack_h2(v.z, v.w);
            *(uint2*)(x + row*(XPITCH*2) + (col << 3)) = hp;
        }
    }
    __syncthreads();   // X visible; mbarrier inits visible to all warps

    // warp tiling
    int m0  = (wid & 3) * 48;
    int lw0 = (wid >> 2) * 32;
    int g = lane >> 2, t = lane & 3;
    int lmr = (lane & 7) | (((lane >> 3) & 1) << 3);  // ldmatrix row within 16
    int lmc = (lane >> 4) << 3;                        // 0 or 8

    float d[3][4][4];
    #pragma unroll
    for (int a = 0; a < 3; a++)
        #pragma unroll
        for (int nt = 0; nt < 4; nt++)
            #pragma unroll
            for (int q = 0; q < 4; q++) d[a][nt][q] = 0.f;

    const uint32_t x_b = base + SM_X;

    for (int ci = 0; ci < NCHUNK; ci++){
        if (ci == 6){
            // ---- epilogue 1: t = relu(v+bv)*ctx -> fp16 back into X smem ----
            __syncthreads();   // all warps finished GEMM1 X reads
            #pragma unroll
            for (int mt = 0; mt < 3; mt++){
                #pragma unroll
                for (int nt = 0; nt < 4; nt++){
                    int o0 = m0 + mt*16 + g;
                    int l  = lw0 + nt*8 + t*2;
                    #pragma unroll
                    for (int h = 0; h < 2; h++){
                        int o = o0 + h*8;
                        float v0 = fmaxf(d[mt][nt][2*h]     + bv_s[o], 0.f) * ctx_s[o];
                        float v1 = fmaxf(d[mt][nt][2*h + 1] + bv_s[o], 0.f) * ctx_s[o];
                        *(uint32_t*)(dsm + SM_X + o*(XPITCH*2) + l*2) = pack_h2(v0, v1);
                    }
                }
            }
            #pragma unroll
            for (int a = 0; a < 3; a++)
                #pragma unroll
                for (int nt = 0; nt < 4; nt++)
                    #pragma unroll
                    for (int q = 0; q < 4; q++) d[a][nt][q] = 0.f;
            __syncthreads();   // new X visible before GEMM2 reads
        }

        int buf = ci & 1;
        uint32_t fullb  = buf ? full1  : full0;
        uint32_t emptyb = buf ? empty1 : empty0;
        MBAR_WAIT_ACQ(fullb, (ci >> 1) & 1);
        uint32_t w_b = base + (buf ? SM_W1 : SM_W0);
        int kc32 = (ci < 6 ? ci : ci - 6) * 32;

        #pragma unroll
        for (int ks = 0; ks < 2; ks++){
            uint32_t Ah[3][4];
            #pragma unroll
            for (int mt = 0; mt < 3; mt++){
                uint32_t arow = (uint32_t)((m0 + mt*16 + lmr)*WPITCH + ks*16 + lmc) * 2u;
                ldsm4(Ah[mt], w_b + arow);
            }
            int kg = kc32 + ks*16;
            #pragma unroll
            for (int ntp = 0; ntp < 2; ntp++){
                uint32_t boff = (uint32_t)((kg + lmr)*XPITCH + lw0 + ntp*16 + lmc) * 2u;
                uint32_t Bh[4];
                ldsm4t(Bh, x_b + boff);
                #pragma unroll
                for (int mt = 0; mt < 3; mt++){
                    mma16816(d[mt][ntp*2],     Ah[mt], Bh[0], Bh[1]);
                    mma16816(d[mt][ntp*2 + 1], Ah[mt], Bh[2], Bh[3]);
                }
            }
        }

        // this warp is done reading chunk ci's W buffer
        __syncwarp();
        if (lane == 0) MBAR_ARRIVE(emptyb);   // release: orders our ldsm reads before the arrive

        // producer: once all 8 warps drained this buffer, refill with chunk ci+2
        if (tid == 0 && ci < NCHUNK - 2){
            int nc = ci + 2;
            MBAR_WAIT_ACQ(emptyb, (ci >> 1) & 1);
            FENCE_ASYNC();                     // generic reads -> async-proxy write ordering
            MBAR_EXPECT(fullb, CHUNK_B);
            BULK_CP(base + (buf ? SM_W1 : SM_W0),
                    (const char*)g_wpack + (size_t)nc*CHUNK_B, CHUNK_B, fullb);
        }
    }

    // ---- epilogue 2: + bo, store to out [o][l] ----
    float* ob = out + (size_t)b*CSL + (size_t)s*Ll + l0t;
    #pragma unroll
    for (int mt = 0; mt < 3; mt++){
        #pragma unroll
        for (int nt = 0; nt < 4; nt++){
            int o0 = m0 + mt*16 + g;
            int l  = lw0 + nt*8 + t*2;
            #pragma unroll
            for (int h = 0; h < 2; h++){
                int o = o0 + h*8;
                float2 r;
                r.x = d[mt][nt][2*h]     + bo_s[o];
                r.y = d[mt][nt][2*h + 1] + bo_s[o];
                *(float2*)(ob + (size_t)o*SL + l) = r;
            }
        }
    }
}

extern "C" void kernel_launch(void* const* d_in, const int* in_sizes, int n_in,
                              void* d_out, int out_size)
{
    const float* query = (const float*)d_in[0];
    const float* key   = (const float*)d_in[1];
    const float* value = (const float*)d_in[2];
    const float* ipw   = (const float*)d_in[3];
    const float* ipb   = (const float*)d_in[4];
    const float* opw   = (const float*)d_in[5];
    const float* opb   = (const float*)d_in[6];
    float* out = (float*)d_out;

    cudaFuncSetAttribute(k_main, cudaFuncAttributeMaxDynamicSharedMemorySize, DSMEM_BYTES);

    k_stage<<<Bx*Ss, 1024>>>(query, key, ipw, ipb, opw);
    k_main<<<Bx*Ss*(Ll/TL), 256, DSMEM_BYTES>>>(value, ipb, opb, out);
}

// round 16
// speedup vs baseline: 3.0632x; 1.0280x over previous
#include <cuda_runtime.h>
#include <cuda_fp16.h>
#include <cstdint>

// Problem constants: B=4, C=192, S=64, L=512
#define Bx 4
#define Cc 192
#define Ss 64
#define Ll 512
#define SL (Ss*Ll)            // 32768
#define CSL ((size_t)Cc*SL)   // 6291456

#define TL 64                 // l-tile per main-role block

// W packing: per 32-k chunk, SINGLE fp16 image; 192 rows x 40 halves (32 data + 8 pad)
#define WPITCH 40
#define CHUNK_E (Cc*WPITCH)       // 7680 elems
#define CHUNK_B (CHUNK_E*2)       // 15360 bytes
#define NCHUNK 12                 // 0..5 = wv, 6..11 = wo

__device__ __align__(16) __half g_wpack[NCHUNK*CHUNK_E];
__device__ float g_ctx[Bx*Ss*Cc];      // ctx[(b*64+s)*192 + c]
__device__ unsigned int g_flag[Bx*Ss]; // per-bs readiness (==192 when ctx ready)

// X smem: [k=192 rows][l=64], pitch 72 halves
#define XPITCH 72

// dynamic smem layout (bytes) — main role
#define SM_W0   0
#define SM_W1   CHUNK_B                       // 15360
#define SM_X    (2*CHUNK_B)                   // 30720
#define SM_BV   (SM_X + Cc*XPITCH*2)          // 58368
#define SM_BO   (SM_BV + Cc*4)
#define DSMEM_BYTES (SM_BO + Cc*4)            // 59904

// ---------------- PTX helpers (base sm_103 target only) ----------------
__device__ __forceinline__ uint32_t smem_u32(const void* p){
    return (uint32_t)__cvta_generic_to_shared(p);
}
#define MBAR_INIT(a, n)  asm volatile("mbarrier.init.shared.b64 [%0], %1;" :: "r"(a), "r"(n) : "memory")
#define MBAR_EXPECT(a, n) asm volatile("mbarrier.arrive.expect_tx.shared.b64 _, [%0], %1;" :: "r"(a), "r"(n) : "memory")
#define MBAR_ARRIVE(a)   asm volatile("mbarrier.arrive.shared.b64 _, [%0];" :: "r"(a) : "memory")
// ACQUIRE wait; bounded: protocol bug => wrong answer, never a hang.
#define MBAR_WAIT_ACQ(a, ph) do { \
    uint32_t _m = (a); uint32_t _p = (ph); uint32_t _done = 0; \
    for (int _i = 0; _i < 2000000 && !_done; _i++){ \
        asm volatile("{\n\t.reg .pred p;\n\t" \
            "mbarrier.try_wait.parity.acquire.cta.shared::cta.b64 p, [%1], %2;\n\t" \
            "selp.b32 %0, 1, 0, p;\n\t}" : "=r"(_done) : "r"(_m), "r"(_p) : "memory"); \
    } } while(0)
#define BULK_CP(dst, src, bytes, mbar) \
    asm volatile("cp.async.bulk.shared::cta.global.mbarrier::complete_tx::bytes [%0], [%1], %2, [%3];" \
        :: "r"(dst), "l"(src), "r"(bytes), "r"(mbar) : "memory")
#define FENCE_ASYNC() asm volatile("fence.proxy.async.shared::cta;" ::: "memory")

__device__ __forceinline__ void ldsm4(uint32_t r[4], uint32_t a){
    asm volatile("ldmatrix.sync.aligned.m8n8.x4.shared.b16 {%0,%1,%2,%3}, [%4];"
        : "=r"(r[0]), "=r"(r[1]), "=r"(r[2]), "=r"(r[3]) : "r"(a));
}
__device__ __forceinline__ void ldsm4t(uint32_t r[4], uint32_t a){
    asm volatile("ldmatrix.sync.aligned.m8n8.x4.trans.shared.b16 {%0,%1,%2,%3}, [%4];"
        : "=r"(r[0]), "=r"(r[1]), "=r"(r[2]), "=r"(r[3]) : "r"(a));
}
__device__ __forceinline__ void mma16816(float d[4], const uint32_t a[4], uint32_t b0, uint32_t b1){
    asm volatile("mma.sync.aligned.m16n8k16.row.col.f32.f16.f16.f32 "
        "{%0,%1,%2,%3}, {%4,%5,%6,%7}, {%8,%9}, {%0,%1,%2,%3};"
        : "+f"(d[0]), "+f"(d[1]), "+f"(d[2]), "+f"(d[3])
        : "r"(a[0]), "r"(a[1]), "r"(a[2]), "r"(a[3]), "r"(b0), "r"(b1));
}
__device__ __forceinline__ uint32_t pack_h2(float x, float y){
    __half a = __float2half(x), b = __float2half(y);
    return ((uint32_t)__half_as_ushort(b) << 16) | (uint32_t)__half_as_ushort(a);
}

// ---------------- K0: weight pack + flag reset (graph-replay safe) ----------------
__global__ void __launch_bounds__(256) k_prep(const float* __restrict__ ipw,
                                              const float* __restrict__ opw){
    int i = blockIdx.x*256 + threadIdx.x;
    if (i < Bx*Ss) g_flag[i] = 0u;
    if (i >= Cc*Cc) return;
    int n = i / Cc, k = i % Cc;
    int kc = k >> 5, kk = k & 31;
    g_wpack[kc*CHUNK_E + n*WPITCH + kk] =
        __float2half(ipw[(size_t)(1 + Cc + n)*Cc + k]);          // wv[n][k]
    g_wpack[(6 + kc)*CHUNK_E + n*WPITCH + kk] =
        __float2half(opw[(size_t)n*Cc + k]);                      // wo[n][k]
}

// ---------------- K1: FUSED stage + main, role-split by blockIdx ----------------
// bids 0..255: STAGE role (one bs each). bids 256..2303: MAIN role ((bs,lt)).
// Stage publishes ctx via 192 release-atomicAdds on g_flag[bs]; main acquires at chunk 6.
__global__ void __launch_bounds__(256, 3) k_fused(
    const float* __restrict__ query, const float* __restrict__ key,
    const float* __restrict__ value,
    const float* __restrict__ ipw,   const float* __restrict__ ipb,
    const float* __restrict__ opb,   float* __restrict__ out)
{
    extern __shared__ char dsm[];
    int tid = threadIdx.x;
    int lane = tid & 31, wid = tid >> 5;

    if (blockIdx.x < (unsigned)(Bx*Ss)){
        // ======================= STAGE ROLE =======================
        float* wq_s = (float*)dsm;            // 192
        float* sc_s = (float*)dsm + 192;      // 512
        float* kb_s = (float*)dsm + 704;      // 192
        float* red  = (float*)dsm + 896;      // 8
        float* bc   = (float*)dsm + 904;      // 1

        int bs = blockIdx.x;
        int b = bs >> 6, s = bs & 63;

        if (tid < Cc) wq_s[tid] = ipw[tid];
        __syncthreads();

        // q for l = 2*tid, 2*tid+1 (R11-proven: 29.7us shape)
        const float* qb = query + (size_t)b*CSL + (size_t)s*Ll + 2*tid;
        float q0 = ipb[0], q1 = ipb[0];
        #pragma unroll 8
        for (int c = 0; c < Cc; c++){
            float w = wq_s[c];
            float2 v = *(const float2*)(qb + (size_t)c*SL);
            q0 = fmaf(w, v.x, q0);
            q1 = fmaf(w, v.y, q1);
        }

        // softmax over 512 (8 warps)
        float m = fmaxf(q0, q1);
        #pragma unroll
        for (int o = 16; o; o >>= 1) m = fmaxf(m, __shfl_xor_sync(0xffffffffu, m, o));
        if (!lane) red[wid] = m;
        __syncthreads();
        if (tid == 0){ float mm = red[0]; for (int i = 1; i < 8; i++) mm = fmaxf(mm, red[i]); *bc = mm; }
        __syncthreads();
        float M = *bc;
        float e0 = expf(q0 - M), e1 = expf(q1 - M);
        float sum = e0 + e1;
        #pragma unroll
        for (int o = 16; o; o >>= 1) sum += __shfl_xor_sync(0xffffffffu, sum, o);
        __syncthreads();
        if (!lane) red[wid] = sum;
        __syncthreads();
        if (tid == 0){ float ss = 0.f; for (int i = 0; i < 8; i++) ss += red[i]; *bc = 1.f/ss; }
        __syncthreads();
        float inv = *bc;
        sc_s[2*tid]     = e0 * inv;
        sc_s[2*tid + 1] = e1 * inv;
        __syncthreads();

        // kbar: 4 passes, 8 warps x 6 rows each, float4 streams
        #pragma unroll
        for (int cg = 0; cg < 4; cg++){
            int c0 = cg*48 + wid*6;
            const float* kb = key + (size_t)b*CSL + (size_t)s*Ll + (size_t)c0*SL + 4*lane;
            float acc[6];
            #pragma unroll
            for (int r = 0; r < 6; r++) acc[r] = 0.f;
            #pragma unroll
            for (int j = 0; j < 4; j++){
                float4 s4 = *(const float4*)(sc_s + 4*lane + 128*j);
                #pragma unroll
                for (int r = 0; r < 6; r++){
                    float4 kv = *(const float4*)(kb + (size_t)r*SL + 128*j);
                    acc[r] = fmaf(kv.x, s4.x, fmaf(kv.y, s4.y, fmaf(kv.z, s4.z, fmaf(kv.w, s4.w, acc[r]))));
                }
            }
            #pragma unroll
            for (int r = 0; r < 6; r++){
                float a = acc[r];
                #pragma unroll
                for (int o = 16; o; o >>= 1) a += __shfl_xor_sync(0xffffffffu, a, o);
                if (!lane) kb_s[c0 + r] = a;
            }
        }
        __syncthreads();

        // ctx + publish (threadfence + relaxed atomic = release chain; reader acquires)
        if (tid < Cc){
            const float* wkr = ipw + (size_t)(1 + tid)*Cc;
            float a = ipb[1 + tid];
            #pragma unroll 8
            for (int j = 0; j < Cc; j++) a = fmaf(wkr[j], kb_s[j], a);
            g_ctx[(size_t)bs*Cc + tid] = a;
            __threadfence();
            atomicAdd(&g_flag[bs], 1u);
        }
        return;
    }

    // ======================= MAIN ROLE =======================
    __shared__ __align__(8) unsigned long long s_mb[4];  // full0, full1, empty0, empty1

    float* bv_s = (float*)(dsm + SM_BV);
    float* bo_s = (float*)(dsm + SM_BO);

    const uint32_t base = smem_u32(dsm);
    const uint32_t full0  = smem_u32(&s_mb[0]);
    const uint32_t full1  = smem_u32(&s_mb[1]);
    const uint32_t empty0 = smem_u32(&s_mb[2]);
    const uint32_t empty1 = smem_u32(&s_mb[3]);

    int blk = blockIdx.x - Bx*Ss;
    int lt = blk & 7;
    int bs = blk >> 3;
    int b = bs >> 6, s = bs & 63;
    int l0t = lt * TL;

    // init + prefetch chunks 0,1 (W packed by k_prep)
    if (tid == 0){
        MBAR_INIT(full0, 1); MBAR_INIT(full1, 1);
        MBAR_INIT(empty0, 8); MBAR_INIT(empty1, 8);
        FENCE_ASYNC();
        MBAR_EXPECT(full0, CHUNK_B);
        BULK_CP(base + SM_W0, (const char*)g_wpack, CHUNK_B, full0);
        MBAR_EXPECT(full1, CHUNK_B);
        BULK_CP(base + SM_W1, (const char*)g_wpack + CHUNK_B, CHUNK_B, full1);
    }

    for (int i = tid; i < Cc; i += 256){
        bv_s[i] = ipb[1 + Cc + i];
        bo_s[i] = opb[i];
    }

    // ---- load value tile [192 c][64 l] fp32 -> fp16 X [k][l] pitch 72 ----
    {
        const float* vb = value + (size_t)b*CSL + (size_t)s*Ll + l0t;
        char* x = dsm + SM_X;
        #pragma unroll
        for (int it = 0; it < 12; it++){
            int f = tid + 256*it;            // 3072 float4 total
            int row = f >> 4, col = f & 15;
            float4 v = *(const float4*)(vb + (size_t)row*SL + (col << 2));
            uint2 hp;
            hp.x = pack_h2(v.x, v.y);
            hp.y = pack_h2(v.z, v.w);
            *(uint2*)(x + row*(XPITCH*2) + (col << 3)) = hp;
        }
    }
    __syncthreads();   // X visible; mbarrier inits visible

    // warp tiling
    int m0  = (wid & 3) * 48;
    int lw0 = (wid >> 2) * 32;
    int g = lane >> 2, t = lane & 3;
    int lmr = (lane & 7) | (((lane >> 3) & 1) << 3);
    int lmc = (lane >> 4) << 3;

    float d[3][4][4];
    #pragma unroll
    for (int a = 0; a < 3; a++)
        #pragma unroll
        for (int nt = 0; nt < 4; nt++)
            #pragma unroll
            for (int q = 0; q < 4; q++) d[a][nt][q] = 0.f;

    const uint32_t x_b = base + SM_X;

    for (int ci = 0; ci < NCHUNK; ci++){
        if (ci == 6){
            // ---- wait for stage role's ctx, then epilogue 1 ----
            __syncthreads();   // all warps finished GEMM1 X reads
            uint32_t fl = 0;
            for (int it = 0; it < 2000000 && fl < 192u; it++)
                asm volatile("ld.acquire.gpu.u32 %0, [%1];"
                             : "=r"(fl) : "l"(&g_flag[bs]) : "memory");
            float ctxv[3][2];
            #pragma unroll
            for (int mt = 0; mt < 3; mt++)
                #pragma unroll
                for (int h = 0; h < 2; h++)
                    ctxv[mt][h] = g_ctx[(size_t)bs*Cc + m0 + mt*16 + g + h*8];

            #pragma unroll
            for (int mt = 0; mt < 3; mt++){
                #pragma unroll
                for (int nt = 0; nt < 4; nt++){
                    int o0 = m0 + mt*16 + g;
                    int l  = lw0 + nt*8 + t*2;
                    #pragma unroll
                    for (int h = 0; h < 2; h++){
                        int o = o0 + h*8;
                        float v0 = fmaxf(d[mt][nt][2*h]     + bv_s[o], 0.f) * ctxv[mt][h];
                        float v1 = fmaxf(d[mt][nt][2*h + 1] + bv_s[o], 0.f) * ctxv[mt][h];
                        *(uint32_t*)(dsm + SM_X + o*(XPITCH*2) + l*2) = pack_h2(v0, v1);
                    }
                }
            }
            #pragma unroll
            for (int a = 0; a < 3; a++)
                #pragma unroll
                for (int nt = 0; nt < 4; nt++)
                    #pragma unroll
                    for (int q = 0; q < 4; q++) d[a][nt][q] = 0.f;
            __syncthreads();   // new X visible before GEMM2 reads
        }

        int buf = ci & 1;
        uint32_t fullb  = buf ? full1  : full0;
        uint32_t emptyb = buf ? empty1 : empty0;
        MBAR_WAIT_ACQ(fullb, (ci >> 1) & 1);
        uint32_t w_b = base + (buf ? SM_W1 : SM_W0);
        int kc32 = (ci < 6 ? ci : ci - 6) * 32;

        #pragma unroll
        for (int ks = 0; ks < 2; ks++){
            uint32_t Ah[3][4];
            #pragma unroll
            for (int mt = 0; mt < 3; mt++){
                uint32_t arow = (uint32_t)((m0 + mt*16 + lmr)*WPITCH + ks*16 + lmc) * 2u;
                ldsm4(Ah[mt], w_b + arow);
            }
            int kg = kc32 + ks*16;
            #pragma unroll
            for (int ntp = 0; ntp < 2; ntp++){
                uint32_t boff = (uint32_t)((kg + lmr)*XPITCH + lw0 + ntp*16 + lmc) * 2u;
                uint32_t Bh[4];
                ldsm4t(Bh, x_b + boff);
                #pragma unroll
                for (int mt = 0; mt < 3; mt++){
                    mma16816(d[mt][ntp*2],     Ah[mt], Bh[0], Bh[1]);
                    mma16816(d[mt][ntp*2 + 1], Ah[mt], Bh[2], Bh[3]);
                }
            }
        }

        __syncwarp();
        if (lane == 0) MBAR_ARRIVE(emptyb);

        if (tid == 0 && ci < NCHUNK - 2){
            int nc = ci + 2;
            MBAR_WAIT_ACQ(emptyb, (ci >> 1) & 1);
            FENCE_ASYNC();
            MBAR_EXPECT(fullb, CHUNK_B);
            BULK_CP(base + (buf ? SM_W1 : SM_W0),
                    (const char*)g_wpack + (size_t)nc*CHUNK_B, CHUNK_B, fullb);
        }
    }

    // ---- epilogue 2: + bo, store ----
    float* ob = out + (size_t)b*CSL + (size_t)s*Ll + l0t;
    #pragma unroll
    for (int mt = 0; mt < 3; mt++){
        #pragma unroll
        for (int nt = 0; nt < 4; nt++){
            int o0 = m0 + mt*16 + g;
            int l  = lw0 + nt*8 + t*2;
            #pragma unroll
            for (int h = 0; h < 2; h++){
                int o = o0 + h*8;
                float2 r;
                r.x = d[mt][nt][2*h]     + bo_s[o];
                r.y = d[mt][nt][2*h + 1] + bo_s[o];
                *(float2*)(ob + (size_t)o*SL + l) = r;
            }
        }
    }
}

extern "C" void kernel_launch(void* const* d_in, const int* in_sizes, int n_in,
                              void* d_out, int out_size)
{
    const float* query = (const float*)d_in[0];
    const float* key   = (const float*)d_in[1];
    const float* value = (const float*)d_in[2];
    const float* ipw   = (const float*)d_in[3];
    const float* ipb   = (const float*)d_in[4];
    const float* opw   = (const float*)d_in[5];
    const float* opb   = (const float*)d_in[6];
    float* out = (float*)d_out;

    cudaFuncSetAttribute(k_fused, cudaFuncAttributeMaxDynamicSharedMemorySize, DSMEM_BYTES);

    k_prep<<<(Cc*Cc + 255)/256, 256>>>(ipw, opw);
    k_fused<<<Bx*Ss + Bx*Ss*(Ll/TL), 256, DSMEM_BYTES>>>(query, key, value, ipw, ipb, opb, out);
}